// round 5
// baseline (speedup 1.0000x reference)
#include <cuda_runtime.h>
#include <cuda_bf16.h>
#include <cstdint>
#include <cstddef>

#define BATCH 4
#define SEQ   4096
#define DIM   512
#define K3Q   (3 * DIM)   // 1536: split-triple K for projections & scores
#define K3P   (3 * SEQ)   // 12288: split-triple K for P @ V

// ------------------------- scratch (device globals) -------------------------
__device__ __align__(128) __nv_bfloat16 g_x3 [BATCH * SEQ * K3Q];          // [16384,1536] HHL
__device__ __align__(128) __nv_bfloat16 g_Wk3[DIM * K3Q];                  // [512,1536]  HLH
__device__ __align__(128) __nv_bfloat16 g_Wq3[DIM * K3Q];
__device__ __align__(128) __nv_bfloat16 g_Wv3[DIM * K3Q];
__device__ __align__(128) __nv_bfloat16 g_K3 [BATCH * SEQ * K3Q];          // HHL (A of scores)
__device__ __align__(128) __nv_bfloat16 g_Q3 [BATCH * SEQ * K3Q];          // HLH (B of scores)
__device__ __align__(128) float         g_V  [BATCH * SEQ * DIM];
__device__ __align__(128) __nv_bfloat16 g_Vt3[(size_t)BATCH * DIM * K3P];  // [512,12288] HLH
__device__ __align__(128) __nv_bfloat16 g_P3 [(size_t)BATCH * SEQ * K3P];  // exp(scores) HHL
__device__ __align__(128) float         g_rs [BATCH * SEQ];                // row sums of exp

// ------------------------------ PTX helpers --------------------------------
__device__ __forceinline__ uint32_t smem_u32(const void* p) {
    uint32_t a;
    asm("{ .reg .u64 t; cvta.to.shared.u64 t, %1; cvt.u32.u64 %0, t; }" : "=r"(a) : "l"(p));
    return a;
}
__device__ __forceinline__ void cp16(uint32_t s, const void* g) {
    asm volatile("cp.async.cg.shared.global [%0], [%1], 16;" :: "r"(s), "l"(g));
}
__device__ __forceinline__ void cp_commit() {
    asm volatile("cp.async.commit_group;" ::: "memory");
}
template <int N>
__device__ __forceinline__ void cp_wait() {
    asm volatile("cp.async.wait_group %0;" :: "n"(N) : "memory");
}
__device__ __forceinline__ void mma16816(float* d, const uint32_t* a, const uint32_t* b) {
    asm volatile(
        "mma.sync.aligned.m16n8k16.row.col.f32.bf16.bf16.f32 "
        "{%0,%1,%2,%3}, {%4,%5,%6,%7}, {%8,%9}, {%0,%1,%2,%3};"
        : "+f"(d[0]), "+f"(d[1]), "+f"(d[2]), "+f"(d[3])
        : "r"(a[0]), "r"(a[1]), "r"(a[2]), "r"(a[3]), "r"(b[0]), "r"(b[1]));
}
__device__ __forceinline__ void ldsm4(uint32_t* r, uint32_t addr) {
    asm volatile("ldmatrix.sync.aligned.m8n8.x4.shared.b16 {%0,%1,%2,%3}, [%4];"
                 : "=r"(r[0]), "=r"(r[1]), "=r"(r[2]), "=r"(r[3]) : "r"(addr));
}

// ---------------------------------------------------------------------------
// bf16 warp-MMA GEMM: C[m,n] = sum_k A[m,k] * B[n,k]
// CTA tile 128x128, BK=64, 3-stage cp.async pipeline (2-ahead, 1 sync/iter),
// 2 CTAs/SM, 8 warps (2m x 4n), warp tile 64x32, ldmatrix fragment loads.
// MODE 0: fp32 C.
// MODE 1: split-bf16 triple out (hi@col, hi@col+offH, lo@col+offL, stride Nout).
// MODE 2: scores: v=exp(alpha*acc) masked (mask[col]==0 -> 0), write split
//         triple (stride Nout, offH/offL) AND atomicAdd per-row sums to rsum.
// MODE 3: fp32 C scaled by 1/rsum[row] (softmax normalization).
// ---------------------------------------------------------------------------
#define BM 128
#define BN 128
#define BK 64
#define STAGES 3
#define ASTR 144                       // smem row bytes: 64*2 + 16 pad (bank-clean)
#define HALF_STAGE (128 * ASTR)        // 18432
#define STAGE_BYTES (2 * HALF_STAGE)   // 36864 (A then B)
#define GSMEM (STAGES * STAGE_BYTES)   // 110592

template <int MODE>
__global__ void __launch_bounds__(256, 2)
gemm_mma(const __nv_bfloat16* __restrict__ A, const __nv_bfloat16* __restrict__ B,
         float* __restrict__ Cf, __nv_bfloat16* __restrict__ Cb,
         int N, int K, size_t Az, size_t Bz, size_t Cz,
         int offH, int offL, int Nout,
         float alpha, const int* __restrict__ mask, float* __restrict__ rsum)
{
    extern __shared__ __align__(128) char smem[];
    const uint32_t sbase = smem_u32(smem);

    const int tid  = threadIdx.x;
    const int z    = blockIdx.z;
    const int bm   = blockIdx.y * BM;
    const int bn   = blockIdx.x * BN;
    const int wid  = tid >> 5;
    const int lane = tid & 31;
    const int wm   = wid >> 2;          // 0..1
    const int wn   = wid & 3;           // 0..3
    const int lr   = lane >> 2;         // 0..7
    const int lc   = lane & 3;          // 0..3

    const __nv_bfloat16* Ag = A + (size_t)z * Az + (size_t)bm * K;
    const __nv_bfloat16* Bg = B + (size_t)z * Bz + (size_t)bn * K;

    const int ldrow = tid >> 1;
    const int ldc0  = (tid & 1) * 4;

    // ldmatrix per-lane offsets (within a stage half)
    const uint32_t a_off = (uint32_t)((wm * 64 + ((lane >> 3) & 1) * 8 + (lane & 7)) * ASTR
                                      + (lane >> 4) * 16);
    const uint32_t b_off = (uint32_t)((wn * 32 + ((lane >> 4) & 1) * 8 + (lane & 7)) * ASTR
                                      + ((lane >> 3) & 1) * 16);

    float acc[4][4][4];
    #pragma unroll
    for (int mt = 0; mt < 4; mt++)
        #pragma unroll
        for (int nt = 0; nt < 4; nt++)
            #pragma unroll
            for (int j = 0; j < 4; j++) acc[mt][nt][j] = 0.0f;

    const int NC = K / BK;

    auto load_stage = [&](int s, int kblk) {
        char* sa = smem + s * STAGE_BYTES;
        char* sb = sa + HALF_STAGE;
        const __nv_bfloat16* ga = Ag + (size_t)kblk * BK + (size_t)ldrow * K;
        const __nv_bfloat16* gb = Bg + (size_t)kblk * BK + (size_t)ldrow * K;
        const uint32_t soa = smem_u32(sa + ldrow * ASTR);
        const uint32_t sob = smem_u32(sb + ldrow * ASTR);
        #pragma unroll
        for (int j = 0; j < 4; j++) {
            const int c = ldc0 + j;
            cp16(soa + c * 16, ga + c * 8);
            cp16(sob + c * 16, gb + c * 8);
        }
    };

    // prologue: 2 stages in flight
    #pragma unroll
    for (int s = 0; s < STAGES - 1; s++) {
        load_stage(s, s);
        cp_commit();
    }

    for (int i = 0; i < NC; i++) {
        if (i + 1 < NC) cp_wait<1>(); else cp_wait<0>();
        __syncthreads();

        const int pf = i + STAGES - 1;
        if (pf < NC) {
            load_stage(pf % STAGES, pf);
            cp_commit();
        }

        const uint32_t sa = sbase + (i % STAGES) * STAGE_BYTES;
        const uint32_t sb = sa + HALF_STAGE;

        #pragma unroll
        for (int k16 = 0; k16 < BK / 16; k16++) {
            uint32_t af[4][4], bf[4][2];
            #pragma unroll
            for (int mt = 0; mt < 4; mt++)
                ldsm4(af[mt], sa + a_off + mt * (16 * ASTR) + k16 * 32);
            #pragma unroll
            for (int ntp = 0; ntp < 2; ntp++) {
                uint32_t br[4];
                ldsm4(br, sb + b_off + ntp * (16 * ASTR) + k16 * 32);
                bf[ntp * 2 + 0][0] = br[0];
                bf[ntp * 2 + 0][1] = br[1];
                bf[ntp * 2 + 1][0] = br[2];
                bf[ntp * 2 + 1][1] = br[3];
            }
            #pragma unroll
            for (int mt = 0; mt < 4; mt++)
                #pragma unroll
                for (int nt = 0; nt < 4; nt++)
                    mma16816(acc[mt][nt], af[mt], bf[nt]);
        }
    }

    // ------------------------------ epilogue -------------------------------
    float* ssum = reinterpret_cast<float*>(smem);   // 128 floats (reuse stage 0)
    if (MODE == 2) {
        __syncthreads();                            // all MMA smem reads done
        if (tid < 128) ssum[tid] = 0.0f;
        __syncthreads();
    }

    #pragma unroll
    for (int mt = 0; mt < 4; mt++) {
        #pragma unroll
        for (int half = 0; half < 2; half++) {
            const int rl  = wm * 64 + mt * 16 + half * 8 + lr;
            const int row = bm + rl;
            float partial = 0.0f;
            float inv = 1.0f;
            if (MODE == 3) inv = 1.0f / rsum[z * SEQ + row];
            #pragma unroll
            for (int nt = 0; nt < 4; nt++) {
                const int col = bn + wn * 32 + nt * 8 + lc * 2;
                float v0 = acc[mt][nt][half * 2 + 0];
                float v1 = acc[mt][nt][half * 2 + 1];
                if (MODE == 1 || MODE == 2) {
                    if (MODE == 2) {
                        const int* mz = mask + z * SEQ;
                        v0 = (mz[col]     == 0) ? 0.0f : __expf(v0 * alpha);
                        v1 = (mz[col + 1] == 0) ? 0.0f : __expf(v1 * alpha);
                        partial += v0 + v1;
                    }
                    __nv_bfloat16 h0 = __float2bfloat16(v0);
                    __nv_bfloat16 h1 = __float2bfloat16(v1);
                    __nv_bfloat16 l0 = __float2bfloat16(v0 - __bfloat162float(h0));
                    __nv_bfloat16 l1 = __float2bfloat16(v1 - __bfloat162float(h1));
                    __nv_bfloat162 hp; hp.x = h0; hp.y = h1;
                    __nv_bfloat162 lp; lp.x = l0; lp.y = l1;
                    __nv_bfloat16* base = Cb + (size_t)z * Cz + (size_t)row * Nout + col;
                    *reinterpret_cast<__nv_bfloat162*>(base)        = hp;
                    *reinterpret_cast<__nv_bfloat162*>(base + offH) = hp;
                    *reinterpret_cast<__nv_bfloat162*>(base + offL) = lp;
                } else {
                    if (MODE == 3) { v0 *= inv; v1 *= inv; }
                    float2 v = make_float2(v0, v1);
                    *reinterpret_cast<float2*>(Cf + (size_t)z * Cz + (size_t)row * N + col) = v;
                }
            }
            if (MODE == 2) atomicAdd(&ssum[rl], partial);
        }
    }

    if (MODE == 2) {
        __syncthreads();
        if (tid < 128) atomicAdd(rsum + z * SEQ + bm + tid, ssum[tid]);
    }
}

// ----------------- fp32 -> split-bf16 triple (row-expanded 3x) -------------
__global__ void split3_kernel(const float* __restrict__ in,
                              __nv_bfloat16* __restrict__ out,
                              int nc, int offH, int offL, int n)
{
    int i = blockIdx.x * blockDim.x + threadIdx.x;
    if (i < n) {
        const int row = i / nc;
        const int c   = i - row * nc;
        const float v = in[i];
        const __nv_bfloat16 h = __float2bfloat16(v);
        const __nv_bfloat16 l = __float2bfloat16(v - __bfloat162float(h));
        __nv_bfloat16* o = out + (size_t)row * (3 * nc);
        o[c]        = h;
        o[c + offH] = h;
        o[c + offL] = l;
    }
}

// V fp32 [b][t][d] -> Vt3 [b][d][12288] HLH: hi at t and 8192+t, lo at 4096+t
__global__ void transpose_split3_kernel(const float* __restrict__ Vin,
                                        __nv_bfloat16* __restrict__ T3)
{
    __shared__ float tile[32][33];
    const int b = blockIdx.z;
    const float* V = Vin + (size_t)b * SEQ * DIM;
    __nv_bfloat16* O = T3 + (size_t)b * DIM * K3P;
    const int d0 = blockIdx.x * 32;
    const int t0 = blockIdx.y * 32;

    #pragma unroll
    for (int r = 0; r < 32; r += 8)
        tile[threadIdx.y + r][threadIdx.x] =
            V[(size_t)(t0 + threadIdx.y + r) * DIM + d0 + threadIdx.x];
    __syncthreads();
    #pragma unroll
    for (int r = 0; r < 32; r += 8) {
        const float v = tile[threadIdx.x][threadIdx.y + r];
        const __nv_bfloat16 h = __float2bfloat16(v);
        const __nv_bfloat16 l = __float2bfloat16(v - __bfloat162float(h));
        __nv_bfloat16* o = O + (size_t)(d0 + threadIdx.y + r) * K3P + t0 + threadIdx.x;
        o[0]            = h;
        o[2 * SEQ]      = h;
        o[SEQ]          = l;
    }
}

__global__ void zero_kernel(float* __restrict__ p, int n)
{
    int i = blockIdx.x * blockDim.x + threadIdx.x;
    if (i < n) p[i] = 0.0f;
}

// ---------------------------------------------------------------------------
extern "C" void kernel_launch(void* const* d_in, const int* in_sizes, int n_in,
                              void* d_out, int out_size)
{
    const float* x    = (const float*)d_in[0];
    const int*   mask = (const int*)  d_in[1];
    const float* Wk   = (const float*)d_in[2];
    const float* Wq   = (const float*)d_in[3];
    const float* Wv   = (const float*)d_in[4];
    float*       out  = (float*)d_out;

    __nv_bfloat16 *x3, *wk3, *wq3, *wv3, *k3, *q3, *vt3, *p3;
    float *vf, *rs;
    cudaGetSymbolAddress((void**)&x3,  g_x3);
    cudaGetSymbolAddress((void**)&wk3, g_Wk3);
    cudaGetSymbolAddress((void**)&wq3, g_Wq3);
    cudaGetSymbolAddress((void**)&wv3, g_Wv3);
    cudaGetSymbolAddress((void**)&k3,  g_K3);
    cudaGetSymbolAddress((void**)&q3,  g_Q3);
    cudaGetSymbolAddress((void**)&vf,  g_V);
    cudaGetSymbolAddress((void**)&vt3, g_Vt3);
    cudaGetSymbolAddress((void**)&p3,  g_P3);
    cudaGetSymbolAddress((void**)&rs,  g_rs);

    cudaFuncSetAttribute(gemm_mma<0>, cudaFuncAttributeMaxDynamicSharedMemorySize, GSMEM);
    cudaFuncSetAttribute(gemm_mma<1>, cudaFuncAttributeMaxDynamicSharedMemorySize, GSMEM);
    cudaFuncSetAttribute(gemm_mma<2>, cudaFuncAttributeMaxDynamicSharedMemorySize, GSMEM);
    cudaFuncSetAttribute(gemm_mma<3>, cudaFuncAttributeMaxDynamicSharedMemorySize, GSMEM);

    const float scale = 0.044194173824159216f;  // 1/sqrt(512)
    const int nx = BATCH * SEQ * DIM;
    const int nw = DIM * DIM;

    // 0) zero row sums
    zero_kernel<<<(BATCH * SEQ + 255) / 256, 256>>>(rs, BATCH * SEQ);

    // 1) split inputs into K-expanded triples
    split3_kernel<<<(nx + 255) / 256, 256>>>(x,  x3,  DIM, DIM,     2 * DIM, nx);  // HHL
    split3_kernel<<<(nw + 255) / 256, 256>>>(Wk, wk3, DIM, 2 * DIM, DIM,     nw);  // HLH
    split3_kernel<<<(nw + 255) / 256, 256>>>(Wq, wq3, DIM, 2 * DIM, DIM,     nw);  // HLH
    split3_kernel<<<(nw + 255) / 256, 256>>>(Wv, wv3, DIM, 2 * DIM, DIM,     nw);  // HLH

    // 2) QKV projections: M=16384, N=512, K'=1536
    {
        dim3 g(DIM / BN, (BATCH * SEQ) / BM, 1);
        gemm_mma<1><<<g, 256, GSMEM>>>(x3, wk3, nullptr, k3,
                                       DIM, K3Q, 0, 0, 0,
                                       DIM, 2 * DIM, K3Q, 1.0f, nullptr, nullptr); // K -> HHL
        gemm_mma<1><<<g, 256, GSMEM>>>(x3, wq3, nullptr, q3,
                                       DIM, K3Q, 0, 0, 0,
                                       2 * DIM, DIM, K3Q, 1.0f, nullptr, nullptr); // Q -> HLH
        gemm_mma<0><<<g, 256, GSMEM>>>(x3, wv3, vf, nullptr,
                                       DIM, K3Q, 0, 0, 0,
                                       0, 0, 0, 1.0f, nullptr, nullptr);           // V -> fp32
    }

    // 3) V -> Vt3
    transpose_split3_kernel<<<dim3(DIM / 32, SEQ / 32, BATCH), dim3(32, 8)>>>(vf, vt3);

    // 4) fused scores + mask + exp + rowsum: P3[b,s,:] = exp(scale*<K,Q>) triple
    {
        dim3 g(SEQ / BN, SEQ / BM, BATCH);
        gemm_mma<2><<<g, 256, GSMEM>>>(k3, q3, nullptr, p3,
                                       SEQ, K3Q,
                                       (size_t)SEQ * K3Q, (size_t)SEQ * K3Q,
                                       (size_t)SEQ * K3P,
                                       SEQ, 2 * SEQ, K3P, scale, mask, rs);
    }

    // 5) out[b,s,d] = (sum_t Pexp[s,t] V[t,d]) / rowsum[s]
    {
        dim3 g(DIM / BN, SEQ / BM, BATCH);
        gemm_mma<3><<<g, 256, GSMEM>>>(p3, vt3, out, nullptr,
                                       DIM, K3P,
                                       (size_t)SEQ * K3P, (size_t)DIM * K3P,
                                       (size_t)SEQ * DIM,
                                       0, 0, 0, 1.0f, nullptr, rs);
    }
}

// round 6
// speedup vs baseline: 1.6134x; 1.6134x over previous
#include <cuda_runtime.h>
#include <cuda_bf16.h>
#include <cstdint>
#include <cstddef>

#define BATCH 4
#define SEQ   4096
#define DIM   512
#define K3Q   (3 * DIM)   // 1536: split-triple K for projections & scores
#define K3P   (3 * SEQ)   // 12288: max split-triple K for P @ V

// ------------------------- scratch (device globals) -------------------------
__device__ __align__(128) __nv_bfloat16 g_x3 [BATCH * SEQ * K3Q];          // HHL
__device__ __align__(128) __nv_bfloat16 g_Wk3[DIM * K3Q];                  // HLH
__device__ __align__(128) __nv_bfloat16 g_Wq3[DIM * K3Q];
__device__ __align__(128) __nv_bfloat16 g_Wv3[DIM * K3Q];
__device__ __align__(128) __nv_bfloat16 g_K3 [BATCH * SEQ * K3Q];          // HHL (A of scores)
__device__ __align__(128) __nv_bfloat16 g_Q3c[BATCH * SEQ * K3Q];          // HLH, row-compacted
__device__ __align__(128) float         g_V  [BATCH * SEQ * DIM];
__device__ __align__(128) __nv_bfloat16 g_Vt3[(size_t)BATCH * DIM * K3P];  // HLH, col-compacted
__device__ __align__(128) __nv_bfloat16 g_P3 [(size_t)BATCH * SEQ * K3P];  // exp(scores) HHL, compacted
__device__ __align__(128) float         g_rs [BATCH * SEQ];                // row sums of exp
__device__ __align__(128) int           g_cmap[BATCH * SEQ];               // t -> compact j (-1 masked)
__device__ __align__(128) int           g_nc  [BATCH];                     // # unmasked
__device__ __align__(128) int           g_ncp [BATCH];                     // padded to 128

// ------------------------------ PTX helpers --------------------------------
__device__ __forceinline__ uint32_t smem_u32(const void* p) {
    uint32_t a;
    asm("{ .reg .u64 t; cvta.to.shared.u64 t, %1; cvt.u32.u64 %0, t; }" : "=r"(a) : "l"(p));
    return a;
}
__device__ __forceinline__ void cp16(uint32_t s, const void* g) {
    asm volatile("cp.async.cg.shared.global [%0], [%1], 16;" :: "r"(s), "l"(g));
}
__device__ __forceinline__ void cp_commit() {
    asm volatile("cp.async.commit_group;" ::: "memory");
}
template <int N>
__device__ __forceinline__ void cp_wait() {
    asm volatile("cp.async.wait_group %0;" :: "n"(N) : "memory");
}
__device__ __forceinline__ void mma16816(float* d, const uint32_t* a, const uint32_t* b) {
    asm volatile(
        "mma.sync.aligned.m16n8k16.row.col.f32.bf16.bf16.f32 "
        "{%0,%1,%2,%3}, {%4,%5,%6,%7}, {%8,%9}, {%0,%1,%2,%3};"
        : "+f"(d[0]), "+f"(d[1]), "+f"(d[2]), "+f"(d[3])
        : "r"(a[0]), "r"(a[1]), "r"(a[2]), "r"(a[3]), "r"(b[0]), "r"(b[1]));
}
__device__ __forceinline__ void ldsm4(uint32_t* r, uint32_t addr) {
    asm volatile("ldmatrix.sync.aligned.m8n8.x4.shared.b16 {%0,%1,%2,%3}, [%4];"
                 : "=r"(r[0]), "=r"(r[1]), "=r"(r[2]), "=r"(r[3]) : "r"(addr));
}

// ---------------------------------------------------------------------------
// bf16 warp-MMA GEMM, CTA 128x128, BK=64, 3-stage cp.async, 2 CTAs/SM.
// MODE 0: fp32 C.
// MODE 1: split-bf16 triple out (hi@c, hi@c+offH, lo@c+offL, stride Nout),
//         optional row compaction via rowmap (skip rows with map<0).
// MODE 2: compacted scores: early-exit CTAs with bn>=ncpad[z]; epilogue
//         v = (col<nc[z]) ? exp(alpha*acc) : 0; triple write with per-batch
//         offsets (np, 2np); rowsum atomics.
// MODE 3: fp32 C scaled by 1/rsum[row]; per-batch K' = 3*ncpad[z].
// ---------------------------------------------------------------------------
#define BM 128
#define BN 128
#define BK 64
#define STAGES 3
#define ASTR 144
#define HALF_STAGE (128 * ASTR)
#define STAGE_BYTES (2 * HALF_STAGE)
#define GSMEM (STAGES * STAGE_BYTES)   // 110592

template <int MODE>
__global__ void __launch_bounds__(256, 2)
gemm_mma(const __nv_bfloat16* __restrict__ A, const __nv_bfloat16* __restrict__ B,
         float* __restrict__ Cf, __nv_bfloat16* __restrict__ Cb,
         int N, int K, size_t Az, size_t Bz, size_t Cz,
         int offH, int offL, int Nout, float alpha,
         float* __restrict__ rsum,
         const int* __restrict__ rowmap,
         const int* __restrict__ ncarr, const int* __restrict__ ncpadarr)
{
    extern __shared__ __align__(128) char smem[];
    const uint32_t sbase = smem_u32(smem);

    const int tid  = threadIdx.x;
    const int z    = blockIdx.z;
    const int bm   = blockIdx.y * BM;
    const int bn   = blockIdx.x * BN;

    int np = 0, nc = 0;
    if (MODE == 2) {
        np = ncpadarr[z];
        if (bn >= np) return;        // whole CTA exits uniformly
        nc = ncarr[z];
    }
    int KK = K;
    if (MODE == 3) KK = 3 * ncpadarr[z];
    const int NC = KK / BK;

    const int wid  = tid >> 5;
    const int lane = tid & 31;
    const int wm   = wid >> 2;
    const int wn   = wid & 3;
    const int lr   = lane >> 2;
    const int lc   = lane & 3;

    const __nv_bfloat16* Ag = A + (size_t)z * Az + (size_t)bm * K;
    const __nv_bfloat16* Bg = B + (size_t)z * Bz + (size_t)bn * K;

    const int ldrow = tid >> 1;
    const int ldc0  = (tid & 1) * 4;

    const uint32_t a_off = (uint32_t)((wm * 64 + ((lane >> 3) & 1) * 8 + (lane & 7)) * ASTR
                                      + (lane >> 4) * 16);
    const uint32_t b_off = (uint32_t)((wn * 32 + ((lane >> 4) & 1) * 8 + (lane & 7)) * ASTR
                                      + ((lane >> 3) & 1) * 16);

    float acc[4][4][4];
    #pragma unroll
    for (int mt = 0; mt < 4; mt++)
        #pragma unroll
        for (int nt = 0; nt < 4; nt++)
            #pragma unroll
            for (int j = 0; j < 4; j++) acc[mt][nt][j] = 0.0f;

    auto load_stage = [&](int s, int kblk) {
        char* sa = smem + s * STAGE_BYTES;
        char* sb = sa + HALF_STAGE;
        const __nv_bfloat16* ga = Ag + (size_t)kblk * BK + (size_t)ldrow * K;
        const __nv_bfloat16* gb = Bg + (size_t)kblk * BK + (size_t)ldrow * K;
        const uint32_t soa = smem_u32(sa + ldrow * ASTR);
        const uint32_t sob = smem_u32(sb + ldrow * ASTR);
        #pragma unroll
        for (int j = 0; j < 4; j++) {
            const int c = ldc0 + j;
            cp16(soa + c * 16, ga + c * 8);
            cp16(sob + c * 16, gb + c * 8);
        }
    };

    #pragma unroll
    for (int s = 0; s < STAGES - 1; s++) {
        load_stage(s, s);
        cp_commit();
    }

    for (int i = 0; i < NC; i++) {
        const int pf = i + STAGES - 1;
        if (pf < NC) load_stage(pf % STAGES, pf);
        cp_commit();
        cp_wait<STAGES - 1>();
        __syncthreads();

        const uint32_t sa = sbase + (i % STAGES) * STAGE_BYTES;
        const uint32_t sb = sa + HALF_STAGE;

        #pragma unroll
        for (int k16 = 0; k16 < BK / 16; k16++) {
            uint32_t af[4][4], bf[4][2];
            #pragma unroll
            for (int mt = 0; mt < 4; mt++)
                ldsm4(af[mt], sa + a_off + mt * (16 * ASTR) + k16 * 32);
            #pragma unroll
            for (int ntp = 0; ntp < 2; ntp++) {
                uint32_t br[4];
                ldsm4(br, sb + b_off + ntp * (16 * ASTR) + k16 * 32);
                bf[ntp * 2 + 0][0] = br[0];
                bf[ntp * 2 + 0][1] = br[1];
                bf[ntp * 2 + 1][0] = br[2];
                bf[ntp * 2 + 1][1] = br[3];
            }
            #pragma unroll
            for (int mt = 0; mt < 4; mt++)
                #pragma unroll
                for (int nt = 0; nt < 4; nt++)
                    mma16816(acc[mt][nt], af[mt], bf[nt]);
        }
        __syncthreads();
    }

    // ------------------------------ epilogue -------------------------------
    float* ssum = reinterpret_cast<float*>(smem);
    if (MODE == 2) {
        if (tid < 128) ssum[tid] = 0.0f;
        __syncthreads();
    }

    const int eoffH = (MODE == 2) ? np     : offH;
    const int eoffL = (MODE == 2) ? 2 * np : offL;

    #pragma unroll
    for (int mt = 0; mt < 4; mt++) {
        #pragma unroll
        for (int half = 0; half < 2; half++) {
            const int rl  = wm * 64 + mt * 16 + half * 8 + lr;
            const int row = bm + rl;
            float partial = 0.0f;
            float inv = 1.0f;
            if (MODE == 3) inv = 1.0f / rsum[z * SEQ + row];

            // MODE 1 row compaction
            size_t orow = (size_t)row;
            bool wr = true;
            if (MODE == 1 && rowmap != nullptr) {
                const int b = row >> 12;           // row / SEQ
                const int j = rowmap[row];
                wr = (j >= 0);
                orow = ((size_t)b << 12) + (size_t)(j < 0 ? 0 : j);
            }

            #pragma unroll
            for (int nt = 0; nt < 4; nt++) {
                const int col = bn + wn * 32 + nt * 8 + lc * 2;
                float v0 = acc[mt][nt][half * 2 + 0];
                float v1 = acc[mt][nt][half * 2 + 1];
                if (MODE == 1 || MODE == 2) {
                    if (MODE == 2) {
                        v0 = (col     < nc) ? __expf(v0 * alpha) : 0.0f;
                        v1 = (col + 1 < nc) ? __expf(v1 * alpha) : 0.0f;
                        partial += v0 + v1;
                    }
                    if (wr) {
                        __nv_bfloat16 h0 = __float2bfloat16(v0);
                        __nv_bfloat16 h1 = __float2bfloat16(v1);
                        __nv_bfloat16 l0 = __float2bfloat16(v0 - __bfloat162float(h0));
                        __nv_bfloat16 l1 = __float2bfloat16(v1 - __bfloat162float(h1));
                        __nv_bfloat162 hp; hp.x = h0; hp.y = h1;
                        __nv_bfloat162 lp; lp.x = l0; lp.y = l1;
                        __nv_bfloat16* base = Cb + (size_t)z * Cz + orow * Nout + col;
                        *reinterpret_cast<__nv_bfloat162*>(base)         = hp;
                        *reinterpret_cast<__nv_bfloat162*>(base + eoffH) = hp;
                        *reinterpret_cast<__nv_bfloat162*>(base + eoffL) = lp;
                    }
                } else {
                    if (MODE == 3) { v0 *= inv; v1 *= inv; }
                    float2 v = make_float2(v0, v1);
                    *reinterpret_cast<float2*>(Cf + (size_t)z * Cz + (size_t)row * N + col) = v;
                }
            }
            if (MODE == 2) atomicAdd(&ssum[rl], partial);
        }
    }

    if (MODE == 2) {
        __syncthreads();
        if (tid < 128) atomicAdd(rsum + z * SEQ + bm + tid, ssum[tid]);
    }
}

// -------------------- mask prefix-scan: one block per batch ----------------
__global__ __launch_bounds__(1024)
void mask_scan_kernel(const int* __restrict__ mask, int* __restrict__ cmap,
                      int* __restrict__ ncarr, int* __restrict__ ncpadarr)
{
    const int b   = blockIdx.x;
    const int tid = threadIdx.x;
    const int* m  = mask + b * SEQ;
    int v[4], s = 0;
    #pragma unroll
    for (int i = 0; i < 4; i++) { v[i] = m[tid * 4 + i]; s += v[i]; }

    const int lane = tid & 31, warp = tid >> 5;
    int sc = s;
    #pragma unroll
    for (int off = 1; off < 32; off <<= 1) {
        int t = __shfl_up_sync(0xffffffffu, sc, off);
        if (lane >= off) sc += t;
    }
    __shared__ int wsum[32];
    if (lane == 31) wsum[warp] = sc;
    __syncthreads();
    if (warp == 0) {
        int w = wsum[lane];
        #pragma unroll
        for (int off = 1; off < 32; off <<= 1) {
            int t = __shfl_up_sync(0xffffffffu, w, off);
            if (lane >= off) w += t;
        }
        wsum[lane] = w;
    }
    __syncthreads();
    int base = (warp > 0 ? wsum[warp - 1] : 0) + sc - s;   // exclusive prefix
    #pragma unroll
    for (int i = 0; i < 4; i++) {
        cmap[b * SEQ + tid * 4 + i] = v[i] ? base : -1;
        base += v[i];
    }
    if (tid == 1023) {
        ncarr[b]    = base;
        ncpadarr[b] = (base + 127) & ~127;
    }
}

// ----------------- fp32 -> split-bf16 triple (row-expanded 3x) -------------
__global__ void split3_kernel(const float* __restrict__ in,
                              __nv_bfloat16* __restrict__ out,
                              int nc, int offH, int offL, int n)
{
    int i = blockIdx.x * blockDim.x + threadIdx.x;
    if (i < n) {
        const int row = i / nc;
        const int c   = i - row * nc;
        const float v = in[i];
        const __nv_bfloat16 h = __float2bfloat16(v);
        const __nv_bfloat16 l = __float2bfloat16(v - __bfloat162float(h));
        __nv_bfloat16* o = out + (size_t)row * (3 * nc);
        o[c]        = h;
        o[c + offH] = h;
        o[c + offL] = l;
    }
}

// V [b][t][d] fp32 -> compacted Vt3c [b][d][3*np] HLH (gather along t)
__global__ void transpose_gather_kernel(const float* __restrict__ Vin,
                                        __nv_bfloat16* __restrict__ T3,
                                        const int* __restrict__ cmap,
                                        const int* __restrict__ ncpadarr)
{
    __shared__ float tile[32][33];
    const int b  = blockIdx.z;
    const int np = ncpadarr[b];
    const float* V = Vin + (size_t)b * SEQ * DIM;
    __nv_bfloat16* O = T3 + (size_t)b * DIM * K3P;
    const int d0 = blockIdx.x * 32;
    const int t0 = blockIdx.y * 32;

    #pragma unroll
    for (int r = 0; r < 32; r += 8)
        tile[threadIdx.y + r][threadIdx.x] =
            V[(size_t)(t0 + threadIdx.y + r) * DIM + d0 + threadIdx.x];
    __syncthreads();
    const int j = cmap[b * SEQ + t0 + threadIdx.x];
    if (j < 0) return;
    #pragma unroll
    for (int r = 0; r < 32; r += 8) {
        const float v = tile[threadIdx.x][threadIdx.y + r];
        const __nv_bfloat16 h = __float2bfloat16(v);
        const __nv_bfloat16 l = __float2bfloat16(v - __bfloat162float(h));
        __nv_bfloat16* o = O + (size_t)(d0 + threadIdx.y + r) * K3P;
        o[j]          = h;
        o[np + j]     = l;
        o[2 * np + j] = h;
    }
}

// zero Vt3c padding columns [nc, np) for all d (keeps 0*garbage out of PV)
__global__ void pad_vt_kernel(__nv_bfloat16* __restrict__ T3,
                              const int* __restrict__ ncarr,
                              const int* __restrict__ ncpadarr)
{
    const int b  = blockIdx.y;
    const int nc = ncarr[b], np = ncpadarr[b];
    const int pad = np - nc;
    if (pad == 0) return;
    const int total = pad * DIM;
    const __nv_bfloat16 zz = __float2bfloat16(0.0f);
    for (int i = blockIdx.x * blockDim.x + threadIdx.x; i < total;
         i += gridDim.x * blockDim.x) {
        const int d = i / pad;
        const int j = nc + (i - d * pad);
        __nv_bfloat16* o = T3 + (size_t)b * DIM * K3P + (size_t)d * K3P;
        o[j] = zz; o[np + j] = zz; o[2 * np + j] = zz;
    }
}

__global__ void zero_kernel(float* __restrict__ p, int n)
{
    int i = blockIdx.x * blockDim.x + threadIdx.x;
    if (i < n) p[i] = 0.0f;
}

// ---------------------------------------------------------------------------
extern "C" void kernel_launch(void* const* d_in, const int* in_sizes, int n_in,
                              void* d_out, int out_size)
{
    const float* x    = (const float*)d_in[0];
    const int*   mask = (const int*)  d_in[1];
    const float* Wk   = (const float*)d_in[2];
    const float* Wq   = (const float*)d_in[3];
    const float* Wv   = (const float*)d_in[4];
    float*       out  = (float*)d_out;

    __nv_bfloat16 *x3, *wk3, *wq3, *wv3, *k3, *q3c, *vt3, *p3;
    float *vf, *rs;
    int *cmap, *ncv, *ncp;
    cudaGetSymbolAddress((void**)&x3,  g_x3);
    cudaGetSymbolAddress((void**)&wk3, g_Wk3);
    cudaGetSymbolAddress((void**)&wq3, g_Wq3);
    cudaGetSymbolAddress((void**)&wv3, g_Wv3);
    cudaGetSymbolAddress((void**)&k3,  g_K3);
    cudaGetSymbolAddress((void**)&q3c, g_Q3c);
    cudaGetSymbolAddress((void**)&vf,  g_V);
    cudaGetSymbolAddress((void**)&vt3, g_Vt3);
    cudaGetSymbolAddress((void**)&p3,  g_P3);
    cudaGetSymbolAddress((void**)&rs,  g_rs);
    cudaGetSymbolAddress((void**)&cmap, g_cmap);
    cudaGetSymbolAddress((void**)&ncv,  g_nc);
    cudaGetSymbolAddress((void**)&ncp,  g_ncp);

    cudaFuncSetAttribute(gemm_mma<0>, cudaFuncAttributeMaxDynamicSharedMemorySize, GSMEM);
    cudaFuncSetAttribute(gemm_mma<1>, cudaFuncAttributeMaxDynamicSharedMemorySize, GSMEM);
    cudaFuncSetAttribute(gemm_mma<2>, cudaFuncAttributeMaxDynamicSharedMemorySize, GSMEM);
    cudaFuncSetAttribute(gemm_mma<3>, cudaFuncAttributeMaxDynamicSharedMemorySize, GSMEM);

    const float scale = 0.044194173824159216f;  // 1/sqrt(512)
    const int nx = BATCH * SEQ * DIM;
    const int nw = DIM * DIM;

    // 0) mask scan + zero rowsums
    mask_scan_kernel<<<BATCH, 1024>>>(mask, cmap, ncv, ncp);
    zero_kernel<<<(BATCH * SEQ + 255) / 256, 256>>>(rs, BATCH * SEQ);

    // 1) split inputs into K-expanded triples
    split3_kernel<<<(nx + 255) / 256, 256>>>(x,  x3,  DIM, DIM,     2 * DIM, nx);  // HHL
    split3_kernel<<<(nw + 255) / 256, 256>>>(Wk, wk3, DIM, 2 * DIM, DIM,     nw);  // HLH
    split3_kernel<<<(nw + 255) / 256, 256>>>(Wq, wq3, DIM, 2 * DIM, DIM,     nw);  // HLH
    split3_kernel<<<(nw + 255) / 256, 256>>>(Wv, wv3, DIM, 2 * DIM, DIM,     nw);  // HLH

    // 2) QKV projections: M=16384, N=512, K'=1536
    {
        dim3 g(DIM / BN, (BATCH * SEQ) / BM, 1);
        gemm_mma<1><<<g, 256, GSMEM>>>(x3, wk3, nullptr, k3,
                                       DIM, K3Q, 0, 0, (size_t)SEQ * K3Q,
                                       DIM, 2 * DIM, K3Q, 1.0f,
                                       nullptr, nullptr, nullptr, nullptr);  // K -> HHL
        gemm_mma<1><<<g, 256, GSMEM>>>(x3, wq3, nullptr, q3c,
                                       DIM, K3Q, 0, 0, (size_t)SEQ * K3Q,
                                       2 * DIM, DIM, K3Q, 1.0f,
                                       nullptr, cmap, nullptr, nullptr);     // Q -> HLH compacted
        gemm_mma<0><<<g, 256, GSMEM>>>(x3, wv3, vf, nullptr,
                                       DIM, K3Q, 0, 0, 0,
                                       0, 0, 0, 1.0f,
                                       nullptr, nullptr, nullptr, nullptr);  // V -> fp32
    }

    // 3) V -> compacted Vt3c (+ zero padding)
    transpose_gather_kernel<<<dim3(DIM / 32, SEQ / 32, BATCH), dim3(32, 8)>>>(vf, vt3, cmap, ncp);
    pad_vt_kernel<<<dim3(64, BATCH), 256>>>(vt3, ncv, ncp);

    // 4) fused compacted scores + exp + rowsum
    {
        dim3 g(SEQ / BN, SEQ / BM, BATCH);
        gemm_mma<2><<<g, 256, GSMEM>>>(k3, q3c, nullptr, p3,
                                       SEQ, K3Q,
                                       (size_t)SEQ * K3Q, (size_t)SEQ * K3Q,
                                       (size_t)SEQ * K3P,
                                       0, 0, K3P, scale,
                                       rs, nullptr, ncv, ncp);
    }

    // 5) out = (P3c @ Vt3c) / rowsum   (per-batch K' = 3*ncpad)
    {
        dim3 g(DIM / BN, SEQ / BM, BATCH);
        gemm_mma<3><<<g, 256, GSMEM>>>(p3, vt3, out, nullptr,
                                       DIM, K3P,
                                       (size_t)SEQ * K3P, (size_t)DIM * K3P,
                                       (size_t)SEQ * DIM,
                                       0, 0, 0, 1.0f,
                                       rs, nullptr, nullptr, ncp);
    }
}

// round 7
// speedup vs baseline: 2.5459x; 1.5779x over previous
#include <cuda_runtime.h>
#include <cuda_bf16.h>
#include <cstdint>
#include <cstddef>

#define BATCH 4
#define SEQ   4096
#define DIM   512
#define MTOT  (BATCH * SEQ)          // 16384
#define NW    (3 * DIM)              // 1536 (QKV merged N)
#define PLX   ((size_t)MTOT * DIM)   // x2 plane stride
#define PLW   ((size_t)NW * DIM)     // Wcat2 plane stride
#define PLK   ((size_t)SEQ * DIM)    // K2/Q2c per-batch plane stride
#define PLP   ((size_t)SEQ * SEQ)    // P2 per-batch plane stride
#define PLV   ((size_t)DIM * SEQ)    // Vt2 per-batch plane stride

// ------------------------- scratch (device globals) -------------------------
__device__ __align__(128) __nv_bfloat16 g_x2 [2 * PLX];                 // x hi|lo planes
__device__ __align__(128) __nv_bfloat16 g_Wc2[2 * PLW];                 // [Wk;Wq;Wv] hi|lo
__device__ __align__(128) __nv_bfloat16 g_K2 [BATCH * 2 * PLK];         // K hi|lo per batch
__device__ __align__(128) __nv_bfloat16 g_Q2c[BATCH * 2 * PLK];         // Q hi|lo, rows compacted
__device__ __align__(128) float         g_V  [MTOT * DIM];
__device__ __align__(128) __nv_bfloat16 g_Vt2[BATCH * 2 * PLV];         // V^T hi|lo, cols compacted
__device__ __align__(128) __nv_bfloat16 g_P2 [(size_t)BATCH * 2 * PLP]; // exp(scores) hi|lo
__device__ __align__(128) float         g_rs [MTOT];
__device__ __align__(128) int           g_cmap[MTOT];
__device__ __align__(128) int           g_nc  [BATCH];
__device__ __align__(128) int           g_ncp [BATCH];

// ------------------------------ PTX helpers --------------------------------
__device__ __forceinline__ uint32_t smem_u32(const void* p) {
    uint32_t a;
    asm("{ .reg .u64 t; cvta.to.shared.u64 t, %1; cvt.u32.u64 %0, t; }" : "=r"(a) : "l"(p));
    return a;
}
__device__ __forceinline__ void cp16(uint32_t s, const void* g) {
    asm volatile("cp.async.cg.shared.global [%0], [%1], 16;" :: "r"(s), "l"(g));
}
__device__ __forceinline__ void cp_commit() {
    asm volatile("cp.async.commit_group;" ::: "memory");
}
template <int N>
__device__ __forceinline__ void cp_wait() {
    asm volatile("cp.async.wait_group %0;" :: "n"(N) : "memory");
}
__device__ __forceinline__ void mma16816(float* d, const uint32_t* a, const uint32_t* b) {
    asm volatile(
        "mma.sync.aligned.m16n8k16.row.col.f32.bf16.bf16.f32 "
        "{%0,%1,%2,%3}, {%4,%5,%6,%7}, {%8,%9}, {%0,%1,%2,%3};"
        : "+f"(d[0]), "+f"(d[1]), "+f"(d[2]), "+f"(d[3])
        : "r"(a[0]), "r"(a[1]), "r"(a[2]), "r"(a[3]), "r"(b[0]), "r"(b[1]));
}
__device__ __forceinline__ void ldsm4(uint32_t* r, uint32_t addr) {
    asm volatile("ldmatrix.sync.aligned.m8n8.x4.shared.b16 {%0,%1,%2,%3}, [%4];"
                 : "=r"(r[0]), "=r"(r[1]), "=r"(r[2]), "=r"(r[3]) : "r"(addr));
}
// XOR swizzle: 64B rows, chunk (16B unit) xor'd by row bits for bank-free ldsm
__device__ __forceinline__ uint32_t swz(int row, int chunk) {
    return (uint32_t)(row * 64 + (((chunk) ^ ((row >> 1) & 3)) << 4));
}

// ---------------------------------------------------------------------------
// split-bf16 2-plane GEMM: acc = Ah*Bh + Ah*Bl + Al*Bh (A,B stored as hi/lo
// planes). CTA 128x128, chunk BK=32 with 3 MMA passes per chunk, 3-stage
// cp.async, 2 CTAs/SM, 8 warps (2m x 4n), ldmatrix + XOR swizzle.
// MODE 0: merged QKV — N-region epilogue: [0,512) K split2 | [512,1024) Q
//         split2 row-compacted | [1024,1536) V fp32.
// MODE 2: compacted scores — exp+mask, split2 out, rowsum atomics.
// MODE 3: PV — fp32 C scaled by 1/rsum; K extent = ncp[z].
// ---------------------------------------------------------------------------
#define BM 128
#define BN 128
#define BKC 32
#define STAGES 3
#define TILE 8192                     // 128 rows * 64 B
#define STAGE_BYTES (4 * TILE)        // Ah | Al | Bh | Bl
#define GSMEM (STAGES * STAGE_BYTES)  // 98304

template <int MODE>
__global__ void __launch_bounds__(256, 2)
gemm2(const __nv_bfloat16* __restrict__ A, const __nv_bfloat16* __restrict__ B,
      int lda, int ldb, size_t Az, size_t Bz, size_t Ap, size_t Bp,
      int Kfix,
      __nv_bfloat16* __restrict__ ObK,   // MODE0: K2   | MODE2: P2
      __nv_bfloat16* __restrict__ ObQ,   // MODE0: Q2c
      float* __restrict__ Of,            // MODE0: V    | MODE3: out
      float* __restrict__ rsum,
      const int* __restrict__ cmap,
      const int* __restrict__ ncv, const int* __restrict__ ncp,
      float alpha)
{
    extern __shared__ __align__(128) char smem[];
    const uint32_t sbase = smem_u32(smem);

    const int tid = threadIdx.x;
    const int z   = blockIdx.z;
    const int bm  = blockIdx.y * BM;
    const int bn  = blockIdx.x * BN;

    int np = 0, nc = 0;
    if (MODE == 2) {
        np = ncp[z];
        if (bn >= np) return;
        nc = ncv[z];
    }
    const int KK = (MODE == 3) ? ncp[z] : Kfix;
    const int NC = KK / BKC;

    const int wid  = tid >> 5;
    const int lane = tid & 31;
    const int wm   = wid >> 2;
    const int wn   = wid & 3;
    const int lr   = lane >> 2;
    const int lc   = lane & 3;

    const __nv_bfloat16* Ag = A + (size_t)z * Az;
    const __nv_bfloat16* Bg = B + (size_t)z * Bz;

    // per-lane ldsm bases
    const int arow_l = wm * 64 + ((lane >> 3) & 1) * 8 + (lane & 7);
    const int akb    = lane >> 4;                     // 0/1 -> k-half
    const int asw    = (arow_l >> 1) & 3;
    const uint32_t abase = (uint32_t)(arow_l * 64);
    const int brow_l = wn * 32 + ((lane >> 4) & 1) * 8 + (lane & 7);
    const int bkb    = (lane >> 3) & 1;
    const int bsw    = (brow_l >> 1) & 3;
    const uint32_t bbase = (uint32_t)(brow_l * 64);

    float acc[4][4][4];
    #pragma unroll
    for (int mt = 0; mt < 4; mt++)
        #pragma unroll
        for (int nt = 0; nt < 4; nt++)
            #pragma unroll
            for (int j = 0; j < 4; j++) acc[mt][nt][j] = 0.0f;

    auto load_stage = [&](int s, int kb) {
        const uint32_t st = sbase + s * STAGE_BYTES;
        const int r = tid >> 1;
        const __nv_bfloat16* ar = Ag + (size_t)(bm + r) * lda + kb * BKC;
        const __nv_bfloat16* br = Bg + (size_t)(bn + r) * ldb + kb * BKC;
        #pragma unroll
        for (int j = 0; j < 2; j++) {
            const int g = (tid & 1) * 2 + j;
            const uint32_t so = swz(r, g);
            cp16(st + so,            ar + g * 8);
            cp16(st + TILE + so,     ar + Ap + g * 8);
            cp16(st + 2 * TILE + so, br + g * 8);
            cp16(st + 3 * TILE + so, br + Bp + g * 8);
        }
    };

    #pragma unroll
    for (int s = 0; s < STAGES - 1; s++) {
        load_stage(s, s);
        cp_commit();
    }

    for (int i = 0; i < NC; i++) {
        const int pf = i + STAGES - 1;
        if (pf < NC) load_stage(pf % STAGES, pf);
        cp_commit();
        cp_wait<STAGES - 1>();
        __syncthreads();

        const uint32_t st  = sbase + (i % STAGES) * STAGE_BYTES;
        const uint32_t sAh = st;
        const uint32_t sAl = st + TILE;
        const uint32_t sBh = st + 2 * TILE;
        const uint32_t sBl = st + 3 * TILE;

        #pragma unroll
        for (int k16 = 0; k16 < 2; k16++) {
            const uint32_t axo = (uint32_t)((((2 * k16 + akb) ^ asw) << 4));
            const uint32_t bxo = (uint32_t)((((2 * k16 + bkb) ^ bsw) << 4));

            uint32_t af[4][4], bh[4][2], bl[4][2];
            #pragma unroll
            for (int mt = 0; mt < 4; mt++)
                ldsm4(af[mt], sAh + abase + mt * 1024 + axo);
            #pragma unroll
            for (int ntp = 0; ntp < 2; ntp++) {
                uint32_t t[4];
                ldsm4(t, sBh + bbase + ntp * 1024 + bxo);
                bh[ntp * 2 + 0][0] = t[0]; bh[ntp * 2 + 0][1] = t[1];
                bh[ntp * 2 + 1][0] = t[2]; bh[ntp * 2 + 1][1] = t[3];
            }
            #pragma unroll
            for (int ntp = 0; ntp < 2; ntp++) {
                uint32_t t[4];
                ldsm4(t, sBl + bbase + ntp * 1024 + bxo);
                bl[ntp * 2 + 0][0] = t[0]; bl[ntp * 2 + 0][1] = t[1];
                bl[ntp * 2 + 1][0] = t[2]; bl[ntp * 2 + 1][1] = t[3];
            }
            #pragma unroll
            for (int mt = 0; mt < 4; mt++)
                #pragma unroll
                for (int nt = 0; nt < 4; nt++)
                    mma16816(acc[mt][nt], af[mt], bh[nt]);
            #pragma unroll
            for (int mt = 0; mt < 4; mt++)
                #pragma unroll
                for (int nt = 0; nt < 4; nt++)
                    mma16816(acc[mt][nt], af[mt], bl[nt]);
            // reuse af for A-lo
            #pragma unroll
            for (int mt = 0; mt < 4; mt++)
                ldsm4(af[mt], sAl + abase + mt * 1024 + axo);
            #pragma unroll
            for (int mt = 0; mt < 4; mt++)
                #pragma unroll
                for (int nt = 0; nt < 4; nt++)
                    mma16816(acc[mt][nt], af[mt], bh[nt]);
        }
        __syncthreads();
    }

    // ------------------------------ epilogue -------------------------------
    float* ssum = reinterpret_cast<float*>(smem);
    if (MODE == 2) {
        if (tid < 128) ssum[tid] = 0.0f;
        __syncthreads();
    }
    const int region = bn >> 9;   // MODE0: 0=K, 1=Q, 2=V

    #pragma unroll
    for (int mt = 0; mt < 4; mt++) {
        #pragma unroll
        for (int half = 0; half < 2; half++) {
            const int rl  = wm * 64 + mt * 16 + half * 8 + lr;
            const int row = bm + rl;
            float partial = 0.0f;
            float inv = 1.0f;
            if (MODE == 3) inv = 1.0f / rsum[z * SEQ + row];

            #pragma unroll
            for (int nt = 0; nt < 4; nt++) {
                const int col = bn + wn * 32 + nt * 8 + lc * 2;
                float v0 = acc[mt][nt][half * 2 + 0];
                float v1 = acc[mt][nt][half * 2 + 1];

                if (MODE == 0) {
                    const int c = col - region * 512;
                    if (region == 2) {
                        *reinterpret_cast<float2*>(Of + (size_t)row * DIM + c) =
                            make_float2(v0, v1);
                    } else {
                        const int b  = row >> 12;
                        int orow = row & 4095;
                        bool wr = true;
                        if (region == 1) {
                            const int j = cmap[row];
                            wr = (j >= 0);
                            orow = (j < 0) ? 0 : j;
                        }
                        if (wr) {
                            __nv_bfloat16 h0 = __float2bfloat16(v0);
                            __nv_bfloat16 h1 = __float2bfloat16(v1);
                            __nv_bfloat16 l0 = __float2bfloat16(v0 - __bfloat162float(h0));
                            __nv_bfloat16 l1 = __float2bfloat16(v1 - __bfloat162float(h1));
                            __nv_bfloat162 hp; hp.x = h0; hp.y = h1;
                            __nv_bfloat162 lp; lp.x = l0; lp.y = l1;
                            __nv_bfloat16* dst = (region == 0 ? ObK : ObQ)
                                + (size_t)b * 2 * PLK + (size_t)orow * DIM + c;
                            *reinterpret_cast<__nv_bfloat162*>(dst)       = hp;
                            *reinterpret_cast<__nv_bfloat162*>(dst + PLK) = lp;
                        }
                    }
                } else if (MODE == 2) {
                    v0 = (col     < nc) ? __expf(v0 * alpha) : 0.0f;
                    v1 = (col + 1 < nc) ? __expf(v1 * alpha) : 0.0f;
                    partial += v0 + v1;
                    __nv_bfloat16 h0 = __float2bfloat16(v0);
                    __nv_bfloat16 h1 = __float2bfloat16(v1);
                    __nv_bfloat16 l0 = __float2bfloat16(v0 - __bfloat162float(h0));
                    __nv_bfloat16 l1 = __float2bfloat16(v1 - __bfloat162float(h1));
                    __nv_bfloat162 hp; hp.x = h0; hp.y = h1;
                    __nv_bfloat162 lp; lp.x = l0; lp.y = l1;
                    __nv_bfloat16* dst = ObK + (size_t)z * 2 * PLP
                                        + (size_t)row * SEQ + col;
                    *reinterpret_cast<__nv_bfloat162*>(dst)       = hp;
                    *reinterpret_cast<__nv_bfloat162*>(dst + PLP) = lp;
                } else {  // MODE 3
                    v0 *= inv; v1 *= inv;
                    *reinterpret_cast<float2*>(Of + (size_t)z * PLK
                        + (size_t)row * DIM + col) = make_float2(v0, v1);
                }
            }
            if (MODE == 2) atomicAdd(&ssum[rl], partial);
        }
    }

    if (MODE == 2) {
        __syncthreads();
        if (tid < 128) atomicAdd(rsum + z * SEQ + bm + tid, ssum[tid]);
    }
}

// -------------------- mask prefix-scan: one block per batch ----------------
__global__ __launch_bounds__(1024)
void mask_scan_kernel(const int* __restrict__ mask, int* __restrict__ cmap,
                      int* __restrict__ ncarr, int* __restrict__ ncpadarr)
{
    const int b   = blockIdx.x;
    const int tid = threadIdx.x;
    const int* m  = mask + b * SEQ;
    int v[4], s = 0;
    #pragma unroll
    for (int i = 0; i < 4; i++) { v[i] = m[tid * 4 + i]; s += v[i]; }

    const int lane = tid & 31, warp = tid >> 5;
    int sc = s;
    #pragma unroll
    for (int off = 1; off < 32; off <<= 1) {
        int t = __shfl_up_sync(0xffffffffu, sc, off);
        if (lane >= off) sc += t;
    }
    __shared__ int wsum[32];
    if (lane == 31) wsum[warp] = sc;
    __syncthreads();
    if (warp == 0) {
        int w = wsum[lane];
        #pragma unroll
        for (int off = 1; off < 32; off <<= 1) {
            int t = __shfl_up_sync(0xffffffffu, w, off);
            if (lane >= off) w += t;
        }
        wsum[lane] = w;
    }
    __syncthreads();
    int base = (warp > 0 ? wsum[warp - 1] : 0) + sc - s;
    #pragma unroll
    for (int i = 0; i < 4; i++) {
        cmap[b * SEQ + tid * 4 + i] = v[i] ? base : -1;
        base += v[i];
    }
    if (tid == 1023) {
        ncarr[b]    = base;
        ncpadarr[b] = (base + 127) & ~127;
    }
}

// ------------------- fp32 -> hi/lo bf16 planes -----------------------------
__global__ void split2_kernel(const float* __restrict__ in,
                              __nv_bfloat16* __restrict__ hi,
                              __nv_bfloat16* __restrict__ lo, int n)
{
    int i = blockIdx.x * blockDim.x + threadIdx.x;
    if (i < n) {
        const float v = in[i];
        const __nv_bfloat16 h = __float2bfloat16(v);
        hi[i] = h;
        lo[i] = __float2bfloat16(v - __bfloat162float(h));
    }
}

// V [b][t][d] fp32 -> compacted Vt2 [b][2][d][j]
__global__ void transpose_gather_kernel(const float* __restrict__ Vin,
                                        __nv_bfloat16* __restrict__ T2,
                                        const int* __restrict__ cmap)
{
    __shared__ float tile[32][33];
    const int b = blockIdx.z;
    const float* V = Vin + (size_t)b * SEQ * DIM;
    __nv_bfloat16* O = T2 + (size_t)b * 2 * PLV;
    const int d0 = blockIdx.x * 32;
    const int t0 = blockIdx.y * 32;

    #pragma unroll
    for (int r = 0; r < 32; r += 8)
        tile[threadIdx.y + r][threadIdx.x] =
            V[(size_t)(t0 + threadIdx.y + r) * DIM + d0 + threadIdx.x];
    __syncthreads();
    const int j = cmap[b * SEQ + t0 + threadIdx.x];
    if (j < 0) return;
    #pragma unroll
    for (int r = 0; r < 32; r += 8) {
        const float v = tile[threadIdx.x][threadIdx.y + r];
        const __nv_bfloat16 h = __float2bfloat16(v);
        const __nv_bfloat16 l = __float2bfloat16(v - __bfloat162float(h));
        __nv_bfloat16* o = O + (size_t)(d0 + threadIdx.y + r) * SEQ + j;
        o[0]   = h;
        o[PLV] = l;
    }
}

// zero Vt2 padding cols [nc, np) in both planes
__global__ void pad_vt_kernel(__nv_bfloat16* __restrict__ T2,
                              const int* __restrict__ ncarr,
                              const int* __restrict__ ncpadarr)
{
    const int b  = blockIdx.y;
    const int nc = ncarr[b], np = ncpadarr[b];
    const int pad = np - nc;
    if (pad == 0) return;
    const int total = pad * DIM;
    const __nv_bfloat16 zz = __float2bfloat16(0.0f);
    for (int i = blockIdx.x * blockDim.x + threadIdx.x; i < total;
         i += gridDim.x * blockDim.x) {
        const int d = i / pad;
        const int j = nc + (i - d * pad);
        __nv_bfloat16* o = T2 + (size_t)b * 2 * PLV + (size_t)d * SEQ + j;
        o[0]   = zz;
        o[PLV] = zz;
    }
}

__global__ void zero_kernel(float* __restrict__ p, int n)
{
    int i = blockIdx.x * blockDim.x + threadIdx.x;
    if (i < n) p[i] = 0.0f;
}

// ---------------------------------------------------------------------------
extern "C" void kernel_launch(void* const* d_in, const int* in_sizes, int n_in,
                              void* d_out, int out_size)
{
    const float* x    = (const float*)d_in[0];
    const int*   mask = (const int*)  d_in[1];
    const float* Wk   = (const float*)d_in[2];
    const float* Wq   = (const float*)d_in[3];
    const float* Wv   = (const float*)d_in[4];
    float*       out  = (float*)d_out;

    __nv_bfloat16 *x2, *wc2, *k2, *q2c, *vt2, *p2;
    float *vf, *rs;
    int *cmap, *ncv, *ncp;
    cudaGetSymbolAddress((void**)&x2,  g_x2);
    cudaGetSymbolAddress((void**)&wc2, g_Wc2);
    cudaGetSymbolAddress((void**)&k2,  g_K2);
    cudaGetSymbolAddress((void**)&q2c, g_Q2c);
    cudaGetSymbolAddress((void**)&vf,  g_V);
    cudaGetSymbolAddress((void**)&vt2, g_Vt2);
    cudaGetSymbolAddress((void**)&p2,  g_P2);
    cudaGetSymbolAddress((void**)&rs,  g_rs);
    cudaGetSymbolAddress((void**)&cmap, g_cmap);
    cudaGetSymbolAddress((void**)&ncv,  g_nc);
    cudaGetSymbolAddress((void**)&ncp,  g_ncp);

    cudaFuncSetAttribute(gemm2<0>, cudaFuncAttributeMaxDynamicSharedMemorySize, GSMEM);
    cudaFuncSetAttribute(gemm2<2>, cudaFuncAttributeMaxDynamicSharedMemorySize, GSMEM);
    cudaFuncSetAttribute(gemm2<3>, cudaFuncAttributeMaxDynamicSharedMemorySize, GSMEM);

    const float scale = 0.044194173824159216f;  // 1/sqrt(512)
    const int nx = MTOT * DIM;
    const int nw = DIM * DIM;

    // 0) mask scan + zero rowsums
    mask_scan_kernel<<<BATCH, 1024>>>(mask, cmap, ncv, ncp);
    zero_kernel<<<(MTOT + 255) / 256, 256>>>(rs, MTOT);

    // 1) split inputs into hi/lo planes (W concatenated [Wk;Wq;Wv])
    split2_kernel<<<(nx + 255) / 256, 256>>>(x,  x2,                    x2  + PLX,              nx);
    split2_kernel<<<(nw + 255) / 256, 256>>>(Wk, wc2,                   wc2 + PLW,              nw);
    split2_kernel<<<(nw + 255) / 256, 256>>>(Wq, wc2 +  512 * DIM,      wc2 + PLW +  512 * DIM, nw);
    split2_kernel<<<(nw + 255) / 256, 256>>>(Wv, wc2 + 1024 * DIM,      wc2 + PLW + 1024 * DIM, nw);

    // 2) merged QKV: M=16384, N=1536, K=512
    {
        dim3 g(NW / BN, MTOT / BM, 1);
        gemm2<0><<<g, 256, GSMEM>>>(x2, wc2, DIM, DIM, 0, 0, PLX, PLW, DIM,
                                    k2, q2c, vf, nullptr, cmap, nullptr, nullptr, 0.0f);
    }

    // 3) V -> compacted Vt2 (+ zero padding)
    transpose_gather_kernel<<<dim3(DIM / 32, SEQ / 32, BATCH), dim3(32, 8)>>>(vf, vt2, cmap);
    pad_vt_kernel<<<dim3(64, BATCH), 256>>>(vt2, ncv, ncp);

    // 4) fused compacted scores + exp + rowsum -> P2 planes
    {
        dim3 g(SEQ / BN, SEQ / BM, BATCH);
        gemm2<2><<<g, 256, GSMEM>>>(k2, q2c, DIM, DIM,
                                    2 * PLK, 2 * PLK, PLK, PLK, DIM,
                                    p2, nullptr, nullptr, rs, nullptr, ncv, ncp, scale);
    }

    // 5) out = (P2 @ Vt2) / rowsum  (per-batch K extent = ncp[z])
    {
        dim3 g(DIM / BN, SEQ / BM, BATCH);
        gemm2<3><<<g, 256, GSMEM>>>(p2, vt2, SEQ, SEQ,
                                    2 * PLP, 2 * PLV, PLP, PLV, 0,
                                    nullptr, nullptr, out, rs, nullptr, ncv, ncp, 0.0f);
    }
}

// round 8
// speedup vs baseline: 2.9920x; 1.1752x over previous
#include <cuda_runtime.h>
#include <cuda_bf16.h>
#include <cstdint>
#include <cstddef>

#define BATCH 4
#define SEQ   4096
#define DIM   512
#define MTOT  (BATCH * SEQ)          // 16384
#define PLX   ((size_t)MTOT * DIM)   // x2 plane stride
#define PLW   ((size_t)(3 * DIM) * DIM) // Wcat2 plane stride (rows: Wk|Wq|Wv)
#define PLK   ((size_t)SEQ * DIM)    // K2/Q2c per-batch plane stride
#define PLP   ((size_t)SEQ * SEQ)    // P2 per-batch plane stride
#define PLV   ((size_t)DIM * SEQ)    // Vt2 per-batch plane stride

// ------------------------- scratch (device globals) -------------------------
__device__ __align__(128) __nv_bfloat16 g_x2 [2 * PLX];
__device__ __align__(128) __nv_bfloat16 g_Wc2[2 * PLW];                 // [Wk;Wq;Wv] hi|lo
__device__ __align__(128) __nv_bfloat16 g_K2 [BATCH * 2 * PLK];
__device__ __align__(128) __nv_bfloat16 g_Q2c[BATCH * 2 * PLK];
__device__ __align__(128) __nv_bfloat16 g_Vt2[BATCH * 2 * PLV];
__device__ __align__(128) __nv_bfloat16 g_P2 [(size_t)BATCH * 2 * PLP];
__device__ __align__(128) float         g_rs [MTOT];
__device__ __align__(128) int           g_cmap[MTOT];
__device__ __align__(128) int           g_nc  [BATCH];
__device__ __align__(128) int           g_ncp [BATCH];

// ------------------------------ PTX helpers --------------------------------
__device__ __forceinline__ uint32_t smem_u32(const void* p) {
    uint32_t a;
    asm("{ .reg .u64 t; cvta.to.shared.u64 t, %1; cvt.u32.u64 %0, t; }" : "=r"(a) : "l"(p));
    return a;
}
__device__ __forceinline__ void cp16(uint32_t s, const void* g) {
    asm volatile("cp.async.cg.shared.global [%0], [%1], 16;" :: "r"(s), "l"(g));
}
__device__ __forceinline__ void cp_commit() {
    asm volatile("cp.async.commit_group;" ::: "memory");
}
template <int N>
__device__ __forceinline__ void cp_wait() {
    asm volatile("cp.async.wait_group %0;" :: "n"(N) : "memory");
}
__device__ __forceinline__ void mma16816(float* d, const uint32_t* a, const uint32_t* b) {
    asm volatile(
        "mma.sync.aligned.m16n8k16.row.col.f32.bf16.bf16.f32 "
        "{%0,%1,%2,%3}, {%4,%5,%6,%7}, {%8,%9}, {%0,%1,%2,%3};"
        : "+f"(d[0]), "+f"(d[1]), "+f"(d[2]), "+f"(d[3])
        : "r"(a[0]), "r"(a[1]), "r"(a[2]), "r"(a[3]), "r"(b[0]), "r"(b[1]));
}
__device__ __forceinline__ void ldsm4(uint32_t* r, uint32_t addr) {
    asm volatile("ldmatrix.sync.aligned.m8n8.x4.shared.b16 {%0,%1,%2,%3}, [%4];"
                 : "=r"(r[0]), "=r"(r[1]), "=r"(r[2]), "=r"(r[3]) : "r"(addr));
}
// XOR swizzle: 64B rows, 16B chunk xor'd by row bits (bank-free ldsm reads)
__device__ __forceinline__ uint32_t swz(int row, int chunk) {
    return (uint32_t)(row * 64 + (((chunk) ^ ((row >> 1) & 3)) << 4));
}

#define BM 128
#define BN 128
#define BKC 32
#define STAGES 3
#define TILE 8192                     // 128 rows * 64 B
#define STAGE_BYTES (4 * TILE)        // Ah | Al | Bh | Bl
#define GSMEM (STAGES * STAGE_BYTES)  // 98304

// Mainloop fragment shared by all kernels (macro to keep one tuned copy).
// Expects: tid, sbase, Ag, Bg, lda, ldb, Ap, Bp, bm, bn, NC, acc declared.
#define GEMM_MAINLOOP()                                                        \
    const int arow_l = wm * 64 + ((lane >> 3) & 1) * 8 + (lane & 7);           \
    const int akb    = lane >> 4;                                              \
    const int asw    = (arow_l >> 1) & 3;                                      \
    const uint32_t abase = (uint32_t)(arow_l * 64);                            \
    const int brow_l = wn * 32 + ((lane >> 4) & 1) * 8 + (lane & 7);           \
    const int bkb    = (lane >> 3) & 1;                                        \
    const int bsw    = (brow_l >> 1) & 3;                                      \
    const uint32_t bbase = (uint32_t)(brow_l * 64);                            \
    auto load_stage = [&](int s, int kb) {                                     \
        const uint32_t st = sbase + s * STAGE_BYTES;                           \
        _Pragma("unroll")                                                      \
        for (int pass = 0; pass < 2; pass++) {                                 \
            const int r = (tid >> 2) + 64 * pass;                              \
            const int c = tid & 3;                                             \
            const uint32_t so = swz(r, c);                                     \
            const __nv_bfloat16* ar = Ag + (size_t)(bm + r) * lda              \
                                         + kb * BKC + c * 8;                   \
            const __nv_bfloat16* br = Bg + (size_t)(bn + r) * ldb              \
                                         + kb * BKC + c * 8;                   \
            cp16(st + so,            ar);                                      \
            cp16(st + TILE + so,     ar + Ap);                                 \
            cp16(st + 2 * TILE + so, br);                                      \
            cp16(st + 3 * TILE + so, br + Bp);                                 \
        }                                                                      \
    };                                                                         \
    _Pragma("unroll")                                                          \
    for (int s = 0; s < STAGES - 1; s++) { load_stage(s, s); cp_commit(); }    \
    for (int i = 0; i < NC; i++) {                                             \
        const int pf = i + STAGES - 1;                                         \
        if (pf < NC) load_stage(pf % STAGES, pf);                              \
        cp_commit();                                                           \
        cp_wait<STAGES - 1>();                                                 \
        __syncthreads();                                                       \
        const uint32_t st  = sbase + (i % STAGES) * STAGE_BYTES;               \
        const uint32_t sAh = st;                                               \
        const uint32_t sAl = st + TILE;                                        \
        const uint32_t sBh = st + 2 * TILE;                                    \
        const uint32_t sBl = st + 3 * TILE;                                    \
        _Pragma("unroll")                                                      \
        for (int k16 = 0; k16 < 2; k16++) {                                    \
            const uint32_t axo = (uint32_t)(((2 * k16 + akb) ^ asw) << 4);     \
            const uint32_t bxo = (uint32_t)(((2 * k16 + bkb) ^ bsw) << 4);     \
            uint32_t af[4][4], bh[4][2], bl[4][2];                             \
            _Pragma("unroll")                                                  \
            for (int mt = 0; mt < 4; mt++)                                     \
                ldsm4(af[mt], sAh + abase + mt * 1024 + axo);                  \
            _Pragma("unroll")                                                  \
            for (int ntp = 0; ntp < 2; ntp++) {                                \
                uint32_t t4[4];                                                \
                ldsm4(t4, sBh + bbase + ntp * 1024 + bxo);                     \
                bh[ntp * 2 + 0][0] = t4[0]; bh[ntp * 2 + 0][1] = t4[1];        \
                bh[ntp * 2 + 1][0] = t4[2]; bh[ntp * 2 + 1][1] = t4[3];        \
            }                                                                  \
            _Pragma("unroll")                                                  \
            for (int ntp = 0; ntp < 2; ntp++) {                                \
                uint32_t t4[4];                                                \
                ldsm4(t4, sBl + bbase + ntp * 1024 + bxo);                     \
                bl[ntp * 2 + 0][0] = t4[0]; bl[ntp * 2 + 0][1] = t4[1];        \
                bl[ntp * 2 + 1][0] = t4[2]; bl[ntp * 2 + 1][1] = t4[3];        \
            }                                                                  \
            _Pragma("unroll")                                                  \
            for (int mt = 0; mt < 4; mt++)                                     \
                _Pragma("unroll")                                              \
                for (int nt = 0; nt < 4; nt++)                                 \
                    mma16816(acc[mt][nt], af[mt], bh[nt]);                     \
            _Pragma("unroll")                                                  \
            for (int mt = 0; mt < 4; mt++)                                     \
                _Pragma("unroll")                                              \
                for (int nt = 0; nt < 4; nt++)                                 \
                    mma16816(acc[mt][nt], af[mt], bl[nt]);                     \
            _Pragma("unroll")                                                  \
            for (int mt = 0; mt < 4; mt++)                                     \
                ldsm4(af[mt], sAl + abase + mt * 1024 + axo);                  \
            _Pragma("unroll")                                                  \
            for (int mt = 0; mt < 4; mt++)                                     \
                _Pragma("unroll")                                              \
                for (int nt = 0; nt < 4; nt++)                                 \
                    mma16816(acc[mt][nt], af[mt], bh[nt]);                     \
        }                                                                      \
        __syncthreads();                                                       \
    }

// ---------------------------------------------------------------------------
// KQ projection: A=x2, B=Wc2 rows [0,1024) (Wk|Wq). N=1024.
// region 0 -> K2 split2; region 1 -> Q2c split2 row-compacted.
// ---------------------------------------------------------------------------
__global__ void __launch_bounds__(256, 2)
gemm_kq(const __nv_bfloat16* __restrict__ A, const __nv_bfloat16* __restrict__ B,
        __nv_bfloat16* __restrict__ K2, __nv_bfloat16* __restrict__ Q2c,
        const int* __restrict__ cmap)
{
    extern __shared__ __align__(128) char smem[];
    const uint32_t sbase = smem_u32(smem);
    const int tid = threadIdx.x;
    const int bm  = blockIdx.y * BM;
    const int bn  = blockIdx.x * BN;
    const int wid = tid >> 5, lane = tid & 31;
    const int wm = wid >> 2, wn = wid & 3;
    const int lr = lane >> 2, lc = lane & 3;

    const __nv_bfloat16* Ag = A;
    const __nv_bfloat16* Bg = B;
    const int lda = DIM, ldb = DIM;
    const size_t Ap = PLX, Bp = PLW;
    const int NC = DIM / BKC;   // 16

    float acc[4][4][4];
    #pragma unroll
    for (int mt = 0; mt < 4; mt++)
        #pragma unroll
        for (int nt = 0; nt < 4; nt++)
            #pragma unroll
            for (int j = 0; j < 4; j++) acc[mt][nt][j] = 0.0f;

    GEMM_MAINLOOP()

    const int region = bn >> 9;   // 0=K, 1=Q
    #pragma unroll
    for (int mt = 0; mt < 4; mt++) {
        #pragma unroll
        for (int half = 0; half < 2; half++) {
            const int row = bm + wm * 64 + mt * 16 + half * 8 + lr;
            const int b   = row >> 12;
            int orow = row & 4095;
            bool wr = true;
            if (region == 1) {
                const int j = cmap[row];
                wr = (j >= 0);
                orow = (j < 0) ? 0 : j;
            }
            if (!wr) continue;
            #pragma unroll
            for (int nt = 0; nt < 4; nt++) {
                const int col = bn + wn * 32 + nt * 8 + lc * 2;
                const int c = col - region * 512;
                float v0 = acc[mt][nt][half * 2 + 0];
                float v1 = acc[mt][nt][half * 2 + 1];
                __nv_bfloat16 h0 = __float2bfloat16(v0);
                __nv_bfloat16 h1 = __float2bfloat16(v1);
                __nv_bfloat16 l0 = __float2bfloat16(v0 - __bfloat162float(h0));
                __nv_bfloat16 l1 = __float2bfloat16(v1 - __bfloat162float(h1));
                __nv_bfloat162 hp; hp.x = h0; hp.y = h1;
                __nv_bfloat162 lp; lp.x = l0; lp.y = l1;
                __nv_bfloat16* dst = (region == 0 ? K2 : Q2c)
                    + (size_t)b * 2 * PLK + (size_t)orow * DIM + c;
                *reinterpret_cast<__nv_bfloat162*>(dst)       = hp;
                *reinterpret_cast<__nv_bfloat162*>(dst + PLK) = lp;
            }
        }
    }
}

// ---------------------------------------------------------------------------
// Fused scores (z<4) + V projection w/ transposed split epilogue (z==4).
// ---------------------------------------------------------------------------
__global__ void __launch_bounds__(256, 2)
gemm_sv(const __nv_bfloat16* __restrict__ K2, const __nv_bfloat16* __restrict__ Q2c,
        const __nv_bfloat16* __restrict__ x2, const __nv_bfloat16* __restrict__ Wv2,
        __nv_bfloat16* __restrict__ P2, __nv_bfloat16* __restrict__ Vt2,
        float* __restrict__ rsum, const int* __restrict__ cmap,
        const int* __restrict__ ncv, const int* __restrict__ ncp, float alpha)
{
    extern __shared__ __align__(128) char smem[];
    const uint32_t sbase = smem_u32(smem);
    const int tid = threadIdx.x;
    const int z   = blockIdx.z;
    const int wid = tid >> 5, lane = tid & 31;
    const int wm = wid >> 2, wn = wid & 3;
    const int lr = lane >> 2, lc = lane & 3;

    const __nv_bfloat16* Ag;
    const __nv_bfloat16* Bg;
    size_t Ap, Bp;
    int bm, bn, np = 0, nc = 0;
    const int lda = DIM, ldb = DIM;

    if (z < 4) {
        np = ncp[z];
        bn = blockIdx.x * BN;
        bm = blockIdx.y * BM;
        if (bn >= np) return;
        nc = ncv[z];
        Ag = K2 + (size_t)z * 2 * PLK;
        Bg = Q2c + (size_t)z * 2 * PLK;
        Ap = PLK; Bp = PLK;
    } else {
        const int id = blockIdx.y * 32 + blockIdx.x;
        if (id >= 512) return;
        bn = (id & 3) * BN;        // d block
        bm = (id >> 2) * BM;       // token block (global, spans batches)
        Ag = x2; Bg = Wv2;
        Ap = PLX; Bp = PLW;
    }
    const int NC = DIM / BKC;      // 16

    float acc[4][4][4];
    #pragma unroll
    for (int mt = 0; mt < 4; mt++)
        #pragma unroll
        for (int nt = 0; nt < 4; nt++)
            #pragma unroll
            for (int j = 0; j < 4; j++) acc[mt][nt][j] = 0.0f;

    GEMM_MAINLOOP()

    if (z < 4) {
        // ---------------- scores epilogue: exp+mask+split2+rowsum ----------
        float* ssum = reinterpret_cast<float*>(smem);
        if (tid < 128) ssum[tid] = 0.0f;
        __syncthreads();
        #pragma unroll
        for (int mt = 0; mt < 4; mt++) {
            #pragma unroll
            for (int half = 0; half < 2; half++) {
                const int rl  = wm * 64 + mt * 16 + half * 8 + lr;
                const int row = bm + rl;
                float partial = 0.0f;
                #pragma unroll
                for (int nt = 0; nt < 4; nt++) {
                    const int col = bn + wn * 32 + nt * 8 + lc * 2;
                    float v0 = acc[mt][nt][half * 2 + 0];
                    float v1 = acc[mt][nt][half * 2 + 1];
                    v0 = (col     < nc) ? __expf(v0 * alpha) : 0.0f;
                    v1 = (col + 1 < nc) ? __expf(v1 * alpha) : 0.0f;
                    partial += v0 + v1;
                    __nv_bfloat16 h0 = __float2bfloat16(v0);
                    __nv_bfloat16 h1 = __float2bfloat16(v1);
                    __nv_bfloat16 l0 = __float2bfloat16(v0 - __bfloat162float(h0));
                    __nv_bfloat16 l1 = __float2bfloat16(v1 - __bfloat162float(h1));
                    __nv_bfloat162 hp; hp.x = h0; hp.y = h1;
                    __nv_bfloat162 lp; lp.x = l0; lp.y = l1;
                    __nv_bfloat16* dst = P2 + (size_t)z * 2 * PLP
                                        + (size_t)row * SEQ + col;
                    *reinterpret_cast<__nv_bfloat162*>(dst)       = hp;
                    *reinterpret_cast<__nv_bfloat162*>(dst + PLP) = lp;
                }
                atomicAdd(&ssum[rl], partial);
            }
        }
        __syncthreads();
        if (tid < 128) atomicAdd(rsum + z * SEQ + bm + tid, ssum[tid]);
    } else {
        // ------------- V epilogue: smem transpose -> split2 Vt2 ------------
        float* sv = reinterpret_cast<float*>(smem);   // [128][129]
        #pragma unroll
        for (int mt = 0; mt < 4; mt++) {
            #pragma unroll
            for (int half = 0; half < 2; half++) {
                const int tok = wm * 64 + mt * 16 + half * 8 + lr;
                #pragma unroll
                for (int nt = 0; nt < 4; nt++) {
                    const int c = wn * 32 + nt * 8 + lc * 2;
                    sv[tok * 129 + c]     = acc[mt][nt][half * 2 + 0];
                    sv[tok * 129 + c + 1] = acc[mt][nt][half * 2 + 1];
                }
            }
        }
        __syncthreads();
        // warp w handles d in [16w, 16w+16); lanes sweep tokens
        #pragma unroll
        for (int tg = 0; tg < 4; tg++) {
            const int tok  = tg * 32 + lane;
            const int gtok = bm + tok;
            const int j = cmap[gtok];
            if (j < 0) continue;
            const int b = gtok >> 12;
            __nv_bfloat16* base = Vt2 + (size_t)b * 2 * PLV + j;
            #pragma unroll
            for (int dd = 0; dd < 16; dd++) {
                const int d = wid * 16 + dd;
                const float v = sv[tok * 129 + d];
                const __nv_bfloat16 h = __float2bfloat16(v);
                const __nv_bfloat16 l = __float2bfloat16(v - __bfloat162float(h));
                __nv_bfloat16* o = base + (size_t)(bn + d) * SEQ;
                o[0]   = h;
                o[PLV] = l;
            }
        }
    }
}

// ---------------------------------------------------------------------------
// PV: out = (P2 @ Vt2) / rsum, per-batch K extent = ncp[z]
// ---------------------------------------------------------------------------
__global__ void __launch_bounds__(256, 2)
gemm_pv(const __nv_bfloat16* __restrict__ P2, const __nv_bfloat16* __restrict__ Vt2,
        float* __restrict__ out, const float* __restrict__ rsum,
        const int* __restrict__ ncp)
{
    extern __shared__ __align__(128) char smem[];
    const uint32_t sbase = smem_u32(smem);
    const int tid = threadIdx.x;
    const int z   = blockIdx.z;
    const int bm  = blockIdx.y * BM;
    const int bn  = blockIdx.x * BN;
    const int wid = tid >> 5, lane = tid & 31;
    const int wm = wid >> 2, wn = wid & 3;
    const int lr = lane >> 2, lc = lane & 3;

    const __nv_bfloat16* Ag = P2  + (size_t)z * 2 * PLP;
    const __nv_bfloat16* Bg = Vt2 + (size_t)z * 2 * PLV;
    const int lda = SEQ, ldb = SEQ;
    const size_t Ap = PLP, Bp = PLV;
    const int NC = ncp[z] / BKC;

    float acc[4][4][4];
    #pragma unroll
    for (int mt = 0; mt < 4; mt++)
        #pragma unroll
        for (int nt = 0; nt < 4; nt++)
            #pragma unroll
            for (int j = 0; j < 4; j++) acc[mt][nt][j] = 0.0f;

    GEMM_MAINLOOP()

    #pragma unroll
    for (int mt = 0; mt < 4; mt++) {
        #pragma unroll
        for (int half = 0; half < 2; half++) {
            const int row = bm + wm * 64 + mt * 16 + half * 8 + lr;
            const float inv = 1.0f / rsum[z * SEQ + row];
            #pragma unroll
            for (int nt = 0; nt < 4; nt++) {
                const int col = bn + wn * 32 + nt * 8 + lc * 2;
                const float v0 = acc[mt][nt][half * 2 + 0] * inv;
                const float v1 = acc[mt][nt][half * 2 + 1] * inv;
                *reinterpret_cast<float2*>(out + (size_t)z * PLK
                    + (size_t)row * DIM + col) = make_float2(v0, v1);
            }
        }
    }
}

// -------------------- mask prefix-scan (+rs zero) --------------------------
__global__ __launch_bounds__(1024)
void mask_scan_kernel(const int* __restrict__ mask, int* __restrict__ cmap,
                      int* __restrict__ ncarr, int* __restrict__ ncpadarr,
                      float* __restrict__ rs)
{
    const int b   = blockIdx.x;
    const int tid = threadIdx.x;
    const int* m  = mask + b * SEQ;
    int v[4], s = 0;
    #pragma unroll
    for (int i = 0; i < 4; i++) {
        v[i] = m[tid * 4 + i];
        s += v[i];
        rs[b * SEQ + tid * 4 + i] = 0.0f;
    }
    const int lane = tid & 31, warp = tid >> 5;
    int sc = s;
    #pragma unroll
    for (int off = 1; off < 32; off <<= 1) {
        int t = __shfl_up_sync(0xffffffffu, sc, off);
        if (lane >= off) sc += t;
    }
    __shared__ int wsum[32];
    if (lane == 31) wsum[warp] = sc;
    __syncthreads();
    if (warp == 0) {
        int w = wsum[lane];
        #pragma unroll
        for (int off = 1; off < 32; off <<= 1) {
            int t = __shfl_up_sync(0xffffffffu, w, off);
            if (lane >= off) w += t;
        }
        wsum[lane] = w;
    }
    __syncthreads();
    int base = (warp > 0 ? wsum[warp - 1] : 0) + sc - s;
    #pragma unroll
    for (int i = 0; i < 4; i++) {
        cmap[b * SEQ + tid * 4 + i] = v[i] ? base : -1;
        base += v[i];
    }
    if (tid == 1023) {
        ncarr[b]    = base;
        ncpadarr[b] = (base + 127) & ~127;
    }
}

// ------------------- fp32 -> hi/lo bf16 planes -----------------------------
__global__ void split2_kernel(const float* __restrict__ in,
                              __nv_bfloat16* __restrict__ hi,
                              __nv_bfloat16* __restrict__ lo, int n)
{
    int i = blockIdx.x * blockDim.x + threadIdx.x;
    if (i < n) {
        const float v = in[i];
        const __nv_bfloat16 h = __float2bfloat16(v);
        hi[i] = h;
        lo[i] = __float2bfloat16(v - __bfloat162float(h));
    }
}

// zero Vt2 padding cols [nc, np) in both planes
__global__ void pad_vt_kernel(__nv_bfloat16* __restrict__ T2,
                              const int* __restrict__ ncarr,
                              const int* __restrict__ ncpadarr)
{
    const int b  = blockIdx.y;
    const int nc = ncarr[b], np = ncpadarr[b];
    const int pad = np - nc;
    if (pad == 0) return;
    const int total = pad * DIM;
    const __nv_bfloat16 zz = __float2bfloat16(0.0f);
    for (int i = blockIdx.x * blockDim.x + threadIdx.x; i < total;
         i += gridDim.x * blockDim.x) {
        const int d = i / pad;
        const int j = nc + (i - d * pad);
        __nv_bfloat16* o = T2 + (size_t)b * 2 * PLV + (size_t)d * SEQ + j;
        o[0]   = zz;
        o[PLV] = zz;
    }
}

// ---------------------------------------------------------------------------
extern "C" void kernel_launch(void* const* d_in, const int* in_sizes, int n_in,
                              void* d_out, int out_size)
{
    const float* x    = (const float*)d_in[0];
    const int*   mask = (const int*)  d_in[1];
    const float* Wk   = (const float*)d_in[2];
    const float* Wq   = (const float*)d_in[3];
    const float* Wv   = (const float*)d_in[4];
    float*       out  = (float*)d_out;

    __nv_bfloat16 *x2, *wc2, *k2, *q2c, *vt2, *p2;
    float *rs;
    int *cmap, *ncv, *ncp;
    cudaGetSymbolAddress((void**)&x2,  g_x2);
    cudaGetSymbolAddress((void**)&wc2, g_Wc2);
    cudaGetSymbolAddress((void**)&k2,  g_K2);
    cudaGetSymbolAddress((void**)&q2c, g_Q2c);
    cudaGetSymbolAddress((void**)&vt2, g_Vt2);
    cudaGetSymbolAddress((void**)&p2,  g_P2);
    cudaGetSymbolAddress((void**)&rs,  g_rs);
    cudaGetSymbolAddress((void**)&cmap, g_cmap);
    cudaGetSymbolAddress((void**)&ncv,  g_nc);
    cudaGetSymbolAddress((void**)&ncp,  g_ncp);

    cudaFuncSetAttribute(gemm_kq, cudaFuncAttributeMaxDynamicSharedMemorySize, GSMEM);
    cudaFuncSetAttribute(gemm_sv, cudaFuncAttributeMaxDynamicSharedMemorySize, GSMEM);
    cudaFuncSetAttribute(gemm_pv, cudaFuncAttributeMaxDynamicSharedMemorySize, GSMEM);

    const float scale = 0.044194173824159216f;  // 1/sqrt(512)
    const int nx = MTOT * DIM;
    const int nw = DIM * DIM;

    // 0) mask scan (+rs zero)
    mask_scan_kernel<<<BATCH, 1024>>>(mask, cmap, ncv, ncp, rs);

    // 1) splits: x + concatenated weights [Wk;Wq;Wv]
    split2_kernel<<<(nx + 255) / 256, 256>>>(x,  x2,               x2  + PLX,               nx);
    split2_kernel<<<(nw + 255) / 256, 256>>>(Wk, wc2,              wc2 + PLW,               nw);
    split2_kernel<<<(nw + 255) / 256, 256>>>(Wq, wc2 +  512 * DIM, wc2 + PLW +  512 * DIM,  nw);
    split2_kernel<<<(nw + 255) / 256, 256>>>(Wv, wc2 + 1024 * DIM, wc2 + PLW + 1024 * DIM,  nw);

    // 1b) zero Vt2 padding (independent of V data; just needs scan)
    pad_vt_kernel<<<dim3(64, BATCH), 256>>>(vt2, ncv, ncp);

    // 2) KQ projections: M=16384, N=1024, K=512
    gemm_kq<<<dim3(1024 / BN, MTOT / BM, 1), 256, GSMEM>>>(x2, wc2, k2, q2c, cmap);

    // 3) fused scores (+exp+rowsum) AND V projection (+transpose split)
    gemm_sv<<<dim3(32, 32, 5), 256, GSMEM>>>(k2, q2c, x2, wc2 + (size_t)1024 * DIM,
                                             p2, vt2, rs, cmap, ncv, ncp, scale);

    // 4) out = (P2 @ Vt2) / rowsum
    gemm_pv<<<dim3(DIM / BN, SEQ / BM, BATCH), 256, GSMEM>>>(p2, vt2, out, rs, ncp);
}

// round 10
// speedup vs baseline: 3.1465x; 1.0516x over previous
#include <cuda_runtime.h>
#include <cuda_bf16.h>
#include <cstdint>
#include <cstddef>

#define BATCH 4
#define SEQ   4096
#define DIM   512
#define MTOT  (BATCH * SEQ)             // 16384
#define PLX   ((size_t)MTOT * DIM)      // x2 plane stride
#define PLW   ((size_t)(3 * DIM) * DIM) // Wcat2 plane stride (rows: Wk|Wq|Wv)
#define PLK   ((size_t)SEQ * DIM)       // K2/Q2c per-batch plane stride
#define PLP   ((size_t)SEQ * SEQ)       // P2 per-batch plane stride
#define PLV   ((size_t)DIM * SEQ)       // Vt2 per-batch plane stride

// ------------------------- scratch (device globals) -------------------------
__device__ __align__(128) __nv_bfloat16 g_x2 [2 * PLX];
__device__ __align__(128) __nv_bfloat16 g_Wc2[2 * PLW];
__device__ __align__(128) __nv_bfloat16 g_K2 [BATCH * 2 * PLK];
__device__ __align__(128) __nv_bfloat16 g_Q2c[BATCH * 2 * PLK];
__device__ __align__(128) __nv_bfloat16 g_Vt2[BATCH * 2 * PLV];
__device__ __align__(128) __nv_bfloat16 g_P2 [(size_t)BATCH * 2 * PLP];
__device__ __align__(128) float         g_rs [MTOT];
__device__ __align__(128) int           g_sel [MTOT];   // j -> t (within batch), 0-padded
__device__ __align__(128) int           g_nc  [BATCH];
__device__ __align__(128) int           g_ncp [BATCH];

// ------------------------------ PTX helpers --------------------------------
__device__ __forceinline__ uint32_t smem_u32(const void* p) {
    uint32_t a;
    asm("{ .reg .u64 t; cvta.to.shared.u64 t, %1; cvt.u32.u64 %0, t; }" : "=r"(a) : "l"(p));
    return a;
}
__device__ __forceinline__ void cp16(uint32_t s, const void* g) {
    asm volatile("cp.async.cg.shared.global [%0], [%1], 16;" :: "r"(s), "l"(g));
}
__device__ __forceinline__ void cp_commit() {
    asm volatile("cp.async.commit_group;" ::: "memory");
}
template <int N>
__device__ __forceinline__ void cp_wait() {
    asm volatile("cp.async.wait_group %0;" :: "n"(N) : "memory");
}
__device__ __forceinline__ void mma16816(float* d, const uint32_t* a, const uint32_t* b) {
    asm volatile(
        "mma.sync.aligned.m16n8k16.row.col.f32.bf16.bf16.f32 "
        "{%0,%1,%2,%3}, {%4,%5,%6,%7}, {%8,%9}, {%0,%1,%2,%3};"
        : "+f"(d[0]), "+f"(d[1]), "+f"(d[2]), "+f"(d[3])
        : "r"(a[0]), "r"(a[1]), "r"(a[2]), "r"(a[3]), "r"(b[0]), "r"(b[1]));
}
__device__ __forceinline__ void ldsm4(uint32_t* r, uint32_t addr) {
    asm volatile("ldmatrix.sync.aligned.m8n8.x4.shared.b16 {%0,%1,%2,%3}, [%4];"
                 : "=r"(r[0]), "=r"(r[1]), "=r"(r[2]), "=r"(r[3]) : "r"(addr));
}
__device__ __forceinline__ uint32_t swz(int row, int chunk) {
    return (uint32_t)(row * 64 + (((chunk) ^ ((row >> 1) & 3)) << 4));
}

#define BM 128
#define BN 128
#define BKC 32
#define STAGES 3
#define TILE 8192
#define STAGE_BYTES (4 * TILE)
#define GSMEM (STAGES * STAGE_BYTES)   // 98304

// Mainloop core. Requires locals: tid, sbase, wm, wn, lane, NC, acc,
// aP0, aP1, bP0, bP1 (row pointers incl. +c0*8), Ap, Bp, so0, so1.
#define GEMM_CORE()                                                            \
    const int arow_l = wm * 64 + ((lane >> 3) & 1) * 8 + (lane & 7);           \
    const int akb    = lane >> 4;                                              \
    const int asw    = (arow_l >> 1) & 3;                                      \
    const uint32_t abase = (uint32_t)(arow_l * 64);                            \
    const int brow_l = wn * 32 + ((lane >> 4) & 1) * 8 + (lane & 7);           \
    const int bkb    = (lane >> 3) & 1;                                        \
    const int bsw    = (brow_l >> 1) & 3;                                      \
    const uint32_t bbase = (uint32_t)(brow_l * 64);                            \
    auto load_stage = [&](int s, int kb) {                                     \
        const uint32_t st = sbase + s * STAGE_BYTES;                           \
        const int ko = kb * BKC;                                               \
        cp16(st + so0,            aP0 + ko);                                   \
        cp16(st + TILE + so0,     aP0 + Ap + ko);                              \
        cp16(st + 2 * TILE + so0, bP0 + ko);                                   \
        cp16(st + 3 * TILE + so0, bP0 + Bp + ko);                              \
        cp16(st + so1,            aP1 + ko);                                   \
        cp16(st + TILE + so1,     aP1 + Ap + ko);                              \
        cp16(st + 2 * TILE + so1, bP1 + ko);                                   \
        cp16(st + 3 * TILE + so1, bP1 + Bp + ko);                              \
    };                                                                         \
    _Pragma("unroll")                                                          \
    for (int s = 0; s < STAGES - 1; s++) { load_stage(s, s); cp_commit(); }    \
    for (int i = 0; i < NC; i++) {                                             \
        const int pf = i + STAGES - 1;                                         \
        if (pf < NC) load_stage(pf % STAGES, pf);                              \
        cp_commit();                                                           \
        cp_wait<STAGES - 1>();                                                 \
        __syncthreads();                                                       \
        const uint32_t st  = sbase + (i % STAGES) * STAGE_BYTES;               \
        const uint32_t sAh = st;                                               \
        const uint32_t sAl = st + TILE;                                        \
        const uint32_t sBh = st + 2 * TILE;                                    \
        const uint32_t sBl = st + 3 * TILE;                                    \
        _Pragma("unroll")                                                      \
        for (int k16 = 0; k16 < 2; k16++) {                                    \
            const uint32_t axo = (uint32_t)(((2 * k16 + akb) ^ asw) << 4);     \
            const uint32_t bxo = (uint32_t)(((2 * k16 + bkb) ^ bsw) << 4);     \
            uint32_t af[4][4], bh[4][2], bl[4][2];                             \
            _Pragma("unroll")                                                  \
            for (int mt = 0; mt < 4; mt++)                                     \
                ldsm4(af[mt], sAh + abase + mt * 1024 + axo);                  \
            _Pragma("unroll")                                                  \
            for (int ntp = 0; ntp < 2; ntp++) {                                \
                uint32_t t4[4];                                                \
                ldsm4(t4, sBh + bbase + ntp * 1024 + bxo);                     \
                bh[ntp * 2 + 0][0] = t4[0]; bh[ntp * 2 + 0][1] = t4[1];        \
                bh[ntp * 2 + 1][0] = t4[2]; bh[ntp * 2 + 1][1] = t4[3];        \
            }                                                                  \
            _Pragma("unroll")                                                  \
            for (int ntp = 0; ntp < 2; ntp++) {                                \
                uint32_t t4[4];                                                \
                ldsm4(t4, sBl + bbase + ntp * 1024 + bxo);                     \
                bl[ntp * 2 + 0][0] = t4[0]; bl[ntp * 2 + 0][1] = t4[1];        \
                bl[ntp * 2 + 1][0] = t4[2]; bl[ntp * 2 + 1][1] = t4[3];        \
            }                                                                  \
            _Pragma("unroll")                                                  \
            for (int mt = 0; mt < 4; mt++)                                     \
                _Pragma("unroll")                                              \
                for (int nt = 0; nt < 4; nt++)                                 \
                    mma16816(acc[mt][nt], af[mt], bh[nt]);                     \
            _Pragma("unroll")                                                  \
            for (int mt = 0; mt < 4; mt++)                                     \
                _Pragma("unroll")                                              \
                for (int nt = 0; nt < 4; nt++)                                 \
                    mma16816(acc[mt][nt], af[mt], bl[nt]);                     \
            _Pragma("unroll")                                                  \
            for (int mt = 0; mt < 4; mt++)                                     \
                ldsm4(af[mt], sAl + abase + mt * 1024 + axo);                  \
            _Pragma("unroll")                                                  \
            for (int mt = 0; mt < 4; mt++)                                     \
                _Pragma("unroll")                                              \
                for (int nt = 0; nt < 4; nt++)                                 \
                    mma16816(acc[mt][nt], af[mt], bh[nt]);                     \
        }                                                                      \
        __syncthreads();                                                       \
    }

#define DECL_ACC()                                                             \
    float acc[4][4][4];                                                        \
    _Pragma("unroll")                                                          \
    for (int mt = 0; mt < 4; mt++)                                             \
        _Pragma("unroll")                                                      \
        for (int nt = 0; nt < 4; nt++)                                         \
            _Pragma("unroll")                                                  \
            for (int j = 0; j < 4; j++) acc[mt][nt][j] = 0.0f;

#define SPLIT2(v0, v1, hp, lp)                                                 \
    __nv_bfloat16 h0 = __float2bfloat16(v0);                                   \
    __nv_bfloat16 h1 = __float2bfloat16(v1);                                   \
    __nv_bfloat16 l0 = __float2bfloat16((v0) - __bfloat162float(h0));          \
    __nv_bfloat16 l1 = __float2bfloat16((v1) - __bfloat162float(h1));          \
    __nv_bfloat162 hp; hp.x = h0; hp.y = h1;                                   \
    __nv_bfloat162 lp; lp.x = l0; lp.y = l1;

// ---------------------------------------------------------------------------
// Projections. z<4: compacted Q|V for batch z (A rows gathered via sel,
// GLOBAL row = z*SEQ + sel[j]).
//   N = 1024: cols [0,512) -> Q2c rows j; cols [512,1024) -> Vt2 (transposed).
// z==4: full K projection (N=512, all 16384 tokens) -> K2.
// ---------------------------------------------------------------------------
__global__ void __launch_bounds__(256, 2)
gemm_proj(const __nv_bfloat16* __restrict__ x2, const __nv_bfloat16* __restrict__ Wc2,
          __nv_bfloat16* __restrict__ K2, __nv_bfloat16* __restrict__ Q2c,
          __nv_bfloat16* __restrict__ Vt2,
          const int* __restrict__ sel, const int* __restrict__ ncv,
          const int* __restrict__ ncp)
{
    extern __shared__ __align__(128) char smem[];
    const uint32_t sbase = smem_u32(smem);
    const int tid = threadIdx.x;
    const int z   = blockIdx.z;
    const int wid = tid >> 5, lane = tid & 31;
    const int wm = wid >> 2, wn = wid & 3;
    const int lr = lane >> 2, lc = lane & 3;

    const int r0 = tid >> 2, c0 = tid & 3;
    const uint32_t so0 = swz(r0, c0);
    const uint32_t so1 = swz(r0 + 64, c0);

    int bm, bn, nc = 0;
    const __nv_bfloat16 *aP0, *aP1, *bP0, *bP1;
    const size_t Ap = PLX, Bp = PLW;

    if (z < 4) {
        bm = blockIdx.y * BM;
        if (bm >= ncp[z]) return;
        nc = ncv[z];
        bn = blockIdx.x * BN;
        // FIX (R9 bug): sel holds WITHIN-BATCH t; global x2 row = z*SEQ + t
        const int t0 = sel[z * SEQ + bm + r0];
        const int t1 = sel[z * SEQ + bm + r0 + 64];
        aP0 = x2 + ((size_t)z * SEQ + t0) * DIM + c0 * 8;
        aP1 = x2 + ((size_t)z * SEQ + t1) * DIM + c0 * 8;
        const __nv_bfloat16* Wqv = Wc2 + (size_t)512 * DIM;
        bP0 = Wqv + (size_t)(bn + r0) * DIM + c0 * 8;
        bP1 = Wqv + (size_t)(bn + r0 + 64) * DIM + c0 * 8;
    } else {
        if (blockIdx.x >= 4) return;
        bm = blockIdx.y * BM;
        bn = blockIdx.x * BN;
        aP0 = x2 + (size_t)(bm + r0) * DIM + c0 * 8;
        aP1 = x2 + (size_t)(bm + r0 + 64) * DIM + c0 * 8;
        bP0 = Wc2 + (size_t)(bn + r0) * DIM + c0 * 8;
        bP1 = Wc2 + (size_t)(bn + r0 + 64) * DIM + c0 * 8;
    }
    const int NC = DIM / BKC;   // 16

    DECL_ACC()
    GEMM_CORE()

    if (z == 4) {
        // K epilogue: split2, rows = global tokens
        #pragma unroll
        for (int mt = 0; mt < 4; mt++) {
            #pragma unroll
            for (int half = 0; half < 2; half++) {
                const int row = bm + wm * 64 + mt * 16 + half * 8 + lr;
                const int b = row >> 12;
                const int orow = row & 4095;
                #pragma unroll
                for (int nt = 0; nt < 4; nt++) {
                    const int c = bn + wn * 32 + nt * 8 + lc * 2;
                    SPLIT2(acc[mt][nt][half * 2], acc[mt][nt][half * 2 + 1], hp, lp)
                    __nv_bfloat16* dst = K2 + (size_t)b * 2 * PLK
                                        + (size_t)orow * DIM + c;
                    *reinterpret_cast<__nv_bfloat162*>(dst)       = hp;
                    *reinterpret_cast<__nv_bfloat162*>(dst + PLK) = lp;
                }
            }
        }
    } else if (bn < 512) {
        // Q epilogue: rows already compacted (j), skip padding
        #pragma unroll
        for (int mt = 0; mt < 4; mt++) {
            #pragma unroll
            for (int half = 0; half < 2; half++) {
                const int j = bm + wm * 64 + mt * 16 + half * 8 + lr;
                if (j >= nc) continue;
                #pragma unroll
                for (int nt = 0; nt < 4; nt++) {
                    const int c = bn + wn * 32 + nt * 8 + lc * 2;
                    SPLIT2(acc[mt][nt][half * 2], acc[mt][nt][half * 2 + 1], hp, lp)
                    __nv_bfloat16* dst = Q2c + (size_t)z * 2 * PLK
                                        + (size_t)j * DIM + c;
                    *reinterpret_cast<__nv_bfloat162*>(dst)       = hp;
                    *reinterpret_cast<__nv_bfloat162*>(dst + PLK) = lp;
                }
            }
        }
    } else {
        // V epilogue: smem transpose -> split2 compacted Vt2
        float* sv = reinterpret_cast<float*>(smem);   // [128][129]
        #pragma unroll
        for (int mt = 0; mt < 4; mt++) {
            #pragma unroll
            for (int half = 0; half < 2; half++) {
                const int tok = wm * 64 + mt * 16 + half * 8 + lr;
                #pragma unroll
                for (int nt = 0; nt < 4; nt++) {
                    const int c = wn * 32 + nt * 8 + lc * 2;
                    sv[tok * 129 + c]     = acc[mt][nt][half * 2 + 0];
                    sv[tok * 129 + c + 1] = acc[mt][nt][half * 2 + 1];
                }
            }
        }
        __syncthreads();
        const int d0 = bn - 512;
        #pragma unroll
        for (int tg = 0; tg < 4; tg++) {
            const int tok = tg * 32 + lane;
            const int j   = bm + tok;
            if (j >= nc) continue;
            __nv_bfloat16* base = Vt2 + (size_t)z * 2 * PLV + j;
            #pragma unroll
            for (int dd = 0; dd < 16; dd++) {
                const int d = wid * 16 + dd;
                const float v = sv[tok * 129 + d];
                const __nv_bfloat16 h = __float2bfloat16(v);
                const __nv_bfloat16 l = __float2bfloat16(v - __bfloat162float(h));
                __nv_bfloat16* o = base + (size_t)(d0 + d) * SEQ;
                o[0]   = h;
                o[PLV] = l;
            }
        }
    }
}

// ---------------------------------------------------------------------------
// Scores: P2 = exp(scale * K2 @ Q2c^T) gated by col<nc, + rowsum atomics.
// ---------------------------------------------------------------------------
__global__ void __launch_bounds__(256, 2)
gemm_s(const __nv_bfloat16* __restrict__ K2, const __nv_bfloat16* __restrict__ Q2c,
       __nv_bfloat16* __restrict__ P2, float* __restrict__ rsum,
       const int* __restrict__ ncv, const int* __restrict__ ncp, float alpha)
{
    extern __shared__ __align__(128) char smem[];
    const uint32_t sbase = smem_u32(smem);
    const int tid = threadIdx.x;
    const int z   = blockIdx.z;
    const int bn  = blockIdx.x * BN;
    const int bm  = blockIdx.y * BM;
    const int np  = ncp[z];
    if (bn >= np) return;
    const int nc  = ncv[z];
    const int wid = tid >> 5, lane = tid & 31;
    const int wm = wid >> 2, wn = wid & 3;
    const int lr = lane >> 2, lc = lane & 3;

    const int r0 = tid >> 2, c0 = tid & 3;
    const uint32_t so0 = swz(r0, c0);
    const uint32_t so1 = swz(r0 + 64, c0);

    const __nv_bfloat16* Ab = K2  + (size_t)z * 2 * PLK;
    const __nv_bfloat16* Bb = Q2c + (size_t)z * 2 * PLK;
    const __nv_bfloat16* aP0 = Ab + (size_t)(bm + r0) * DIM + c0 * 8;
    const __nv_bfloat16* aP1 = Ab + (size_t)(bm + r0 + 64) * DIM + c0 * 8;
    const __nv_bfloat16* bP0 = Bb + (size_t)(bn + r0) * DIM + c0 * 8;
    const __nv_bfloat16* bP1 = Bb + (size_t)(bn + r0 + 64) * DIM + c0 * 8;
    const size_t Ap = PLK, Bp = PLK;
    const int NC = DIM / BKC;

    DECL_ACC()
    GEMM_CORE()

    float* ssum = reinterpret_cast<float*>(smem);
    if (tid < 128) ssum[tid] = 0.0f;
    __syncthreads();
    #pragma unroll
    for (int mt = 0; mt < 4; mt++) {
        #pragma unroll
        for (int half = 0; half < 2; half++) {
            const int rl  = wm * 64 + mt * 16 + half * 8 + lr;
            const int row = bm + rl;
            float partial = 0.0f;
            #pragma unroll
            for (int nt = 0; nt < 4; nt++) {
                const int col = bn + wn * 32 + nt * 8 + lc * 2;
                float v0 = acc[mt][nt][half * 2 + 0];
                float v1 = acc[mt][nt][half * 2 + 1];
                v0 = (col     < nc) ? __expf(v0 * alpha) : 0.0f;
                v1 = (col + 1 < nc) ? __expf(v1 * alpha) : 0.0f;
                partial += v0 + v1;
                SPLIT2(v0, v1, hp, lp)
                __nv_bfloat16* dst = P2 + (size_t)z * 2 * PLP
                                    + (size_t)row * SEQ + col;
                *reinterpret_cast<__nv_bfloat162*>(dst)       = hp;
                *reinterpret_cast<__nv_bfloat162*>(dst + PLP) = lp;
            }
            atomicAdd(&ssum[rl], partial);
        }
    }
    __syncthreads();
    if (tid < 128) atomicAdd(rsum + z * SEQ + bm + tid, ssum[tid]);
}

// ---------------------------------------------------------------------------
// PV: out = (P2 @ Vt2) / rsum, per-batch K extent = ncp[z]
// ---------------------------------------------------------------------------
__global__ void __launch_bounds__(256, 2)
gemm_pv(const __nv_bfloat16* __restrict__ P2, const __nv_bfloat16* __restrict__ Vt2,
        float* __restrict__ out, const float* __restrict__ rsum,
        const int* __restrict__ ncp)
{
    extern __shared__ __align__(128) char smem[];
    const uint32_t sbase = smem_u32(smem);
    const int tid = threadIdx.x;
    const int z   = blockIdx.z;
    const int bm  = blockIdx.y * BM;
    const int bn  = blockIdx.x * BN;
    const int wid = tid >> 5, lane = tid & 31;
    const int wm = wid >> 2, wn = wid & 3;
    const int lr = lane >> 2, lc = lane & 3;

    const int r0 = tid >> 2, c0 = tid & 3;
    const uint32_t so0 = swz(r0, c0);
    const uint32_t so1 = swz(r0 + 64, c0);

    const __nv_bfloat16* Ab = P2  + (size_t)z * 2 * PLP;
    const __nv_bfloat16* Bb = Vt2 + (size_t)z * 2 * PLV;
    const __nv_bfloat16* aP0 = Ab + (size_t)(bm + r0) * SEQ + c0 * 8;
    const __nv_bfloat16* aP1 = Ab + (size_t)(bm + r0 + 64) * SEQ + c0 * 8;
    const __nv_bfloat16* bP0 = Bb + (size_t)(bn + r0) * SEQ + c0 * 8;
    const __nv_bfloat16* bP1 = Bb + (size_t)(bn + r0 + 64) * SEQ + c0 * 8;
    const size_t Ap = PLP, Bp = PLV;
    const int NC = ncp[z] / BKC;

    DECL_ACC()
    GEMM_CORE()

    #pragma unroll
    for (int mt = 0; mt < 4; mt++) {
        #pragma unroll
        for (int half = 0; half < 2; half++) {
            const int row = bm + wm * 64 + mt * 16 + half * 8 + lr;
            const float inv = 1.0f / rsum[z * SEQ + row];
            #pragma unroll
            for (int nt = 0; nt < 4; nt++) {
                const int col = bn + wn * 32 + nt * 8 + lc * 2;
                const float v0 = acc[mt][nt][half * 2 + 0] * inv;
                const float v1 = acc[mt][nt][half * 2 + 1] * inv;
                *reinterpret_cast<float2*>(out + (size_t)z * PLK
                    + (size_t)row * DIM + col) = make_float2(v0, v1);
            }
        }
    }
}

// -------------------- mask prefix-scan (+sel build, +rs zero) ---------------
__global__ __launch_bounds__(1024)
void mask_scan_kernel(const int* __restrict__ mask, int* __restrict__ sel,
                      int* __restrict__ ncarr, int* __restrict__ ncpadarr,
                      float* __restrict__ rs)
{
    const int b   = blockIdx.x;
    const int tid = threadIdx.x;
    const int* m  = mask + b * SEQ;
    int v[4], s = 0;
    #pragma unroll
    for (int i = 0; i < 4; i++) {
        v[i] = m[tid * 4 + i];
        s += v[i];
        rs[b * SEQ + tid * 4 + i] = 0.0f;
        sel[b * SEQ + tid * 4 + i] = 0;        // padding default
    }
    const int lane = tid & 31, warp = tid >> 5;
    int sc = s;
    #pragma unroll
    for (int off = 1; off < 32; off <<= 1) {
        int t = __shfl_up_sync(0xffffffffu, sc, off);
        if (lane >= off) sc += t;
    }
    __shared__ int wsum[32];
    if (lane == 31) wsum[warp] = sc;
    __syncthreads();
    if (warp == 0) {
        int w = wsum[lane];
        #pragma unroll
        for (int off = 1; off < 32; off <<= 1) {
            int t = __shfl_up_sync(0xffffffffu, w, off);
            if (lane >= off) w += t;
        }
        wsum[lane] = w;
    }
    __syncthreads();
    int base = (warp > 0 ? wsum[warp - 1] : 0) + sc - s;   // exclusive prefix
    __syncthreads();                                       // zero-fill done
    #pragma unroll
    for (int i = 0; i < 4; i++) {
        if (v[i]) sel[b * SEQ + base] = tid * 4 + i;
        base += v[i];
    }
    if (tid == 1023) {
        ncarr[b]    = base;
        ncpadarr[b] = (base + 127) & ~127;
    }
}

// ------------------- fp32 -> hi/lo bf16 planes -----------------------------
__global__ void split2_kernel(const float* __restrict__ in,
                              __nv_bfloat16* __restrict__ hi,
                              __nv_bfloat16* __restrict__ lo, int n)
{
    int i = blockIdx.x * blockDim.x + threadIdx.x;
    if (i < n) {
        const float v = in[i];
        const __nv_bfloat16 h = __float2bfloat16(v);
        hi[i] = h;
        lo[i] = __float2bfloat16(v - __bfloat162float(h));
    }
}

// zero Vt2 padding cols [nc, np) in both planes
__global__ void pad_vt_kernel(__nv_bfloat16* __restrict__ T2,
                              const int* __restrict__ ncarr,
                              const int* __restrict__ ncpadarr)
{
    const int b  = blockIdx.y;
    const int nc = ncarr[b], np = ncpadarr[b];
    const int pad = np - nc;
    if (pad == 0) return;
    const int total = pad * DIM;
    const __nv_bfloat16 zz = __float2bfloat16(0.0f);
    for (int i = blockIdx.x * blockDim.x + threadIdx.x; i < total;
         i += gridDim.x * blockDim.x) {
        const int d = i / pad;
        const int j = nc + (i - d * pad);
        __nv_bfloat16* o = T2 + (size_t)b * 2 * PLV + (size_t)d * SEQ + j;
        o[0]   = zz;
        o[PLV] = zz;
    }
}

// ---------------------------------------------------------------------------
extern "C" void kernel_launch(void* const* d_in, const int* in_sizes, int n_in,
                              void* d_out, int out_size)
{
    const float* x    = (const float*)d_in[0];
    const int*   mask = (const int*)  d_in[1];
    const float* Wk   = (const float*)d_in[2];
    const float* Wq   = (const float*)d_in[3];
    const float* Wv   = (const float*)d_in[4];
    float*       out  = (float*)d_out;

    __nv_bfloat16 *x2, *wc2, *k2, *q2c, *vt2, *p2;
    float *rs;
    int *sel, *ncv, *ncp;
    cudaGetSymbolAddress((void**)&x2,  g_x2);
    cudaGetSymbolAddress((void**)&wc2, g_Wc2);
    cudaGetSymbolAddress((void**)&k2,  g_K2);
    cudaGetSymbolAddress((void**)&q2c, g_Q2c);
    cudaGetSymbolAddress((void**)&vt2, g_Vt2);
    cudaGetSymbolAddress((void**)&p2,  g_P2);
    cudaGetSymbolAddress((void**)&rs,  g_rs);
    cudaGetSymbolAddress((void**)&sel, g_sel);
    cudaGetSymbolAddress((void**)&ncv, g_nc);
    cudaGetSymbolAddress((void**)&ncp, g_ncp);

    cudaFuncSetAttribute(gemm_proj, cudaFuncAttributeMaxDynamicSharedMemorySize, GSMEM);
    cudaFuncSetAttribute(gemm_s,    cudaFuncAttributeMaxDynamicSharedMemorySize, GSMEM);
    cudaFuncSetAttribute(gemm_pv,   cudaFuncAttributeMaxDynamicSharedMemorySize, GSMEM);

    const float scale = 0.044194173824159216f;  // 1/sqrt(512)
    const int nx = MTOT * DIM;
    const int nw = DIM * DIM;

    // 0) mask scan: sel + counts + rs zero
    mask_scan_kernel<<<BATCH, 1024>>>(mask, sel, ncv, ncp, rs);

    // 1) splits: x + concatenated weights [Wk;Wq;Wv]
    split2_kernel<<<(nx + 255) / 256, 256>>>(x,  x2,               x2  + PLX,              nx);
    split2_kernel<<<(nw + 255) / 256, 256>>>(Wk, wc2,              wc2 + PLW,              nw);
    split2_kernel<<<(nw + 255) / 256, 256>>>(Wq, wc2 +  512 * DIM, wc2 + PLW +  512 * DIM, nw);
    split2_kernel<<<(nw + 255) / 256, 256>>>(Wv, wc2 + 1024 * DIM, wc2 + PLW + 1024 * DIM, nw);

    // 1b) zero Vt2 padding cols
    pad_vt_kernel<<<dim3(64, BATCH), 256>>>(vt2, ncv, ncp);

    // 2) projections: z<4 compacted Q|V per batch; z==4 full K
    gemm_proj<<<dim3(8, 128, 5), 256, GSMEM>>>(x2, wc2, k2, q2c, vt2, sel, ncv, ncp);

    // 3) scores + exp + rowsum
    gemm_s<<<dim3(32, 32, BATCH), 256, GSMEM>>>(k2, q2c, p2, rs, ncv, ncp, scale);

    // 4) out = (P2 @ Vt2) / rowsum
    gemm_pv<<<dim3(DIM / BN, SEQ / BM, BATCH), 256, GSMEM>>>(p2, vt2, out, rs, ncp);
}